// round 4
// baseline (speedup 1.0000x reference)
#include <cuda_runtime.h>
#include <cuda_fp16.h>

// splineGCN: 2-layer SplineConv (K=2), N=50000, E=1.6M, 32 -> 32 -> 10, log_softmax.
// CSR-by-destination structure: build once, gather-reduce both layers (no feature atomics).

#define NMAX 50000
#define EMAX 1600000
#define FULLMASK 0xffffffffu

// ---- scratch ----
__device__ __half2 g_p1 [NMAX * 32];  // packed {h0, h1-h0} per (node, feat)
__device__ float   g_r1 [NMAX * 32];  // x @ root1 + b1
__device__ __half2 g_p2 [NMAX * 16];  // packed {g0, g1-g0}, stride 16 (cols 10..15 zero)
__device__ float   g_r2 [NMAX * 16];
__device__ int     g_degi[NMAX];
__device__ int     g_rs [NMAX];       // CSR row start (exclusive scan of deg)
__device__ int     g_cur[NMAX];       // placement cursors
__device__ int2    g_eidx[EMAX];      // decoded (src, dst)
__device__ int2    g_csr [EMAX];      // dest-sorted {src, float_bits(u)}
__device__ int     g_is64;

// ---- dtype detection: int64 edge_index has all odd 32-bit words zero ----
__global__ void k_detect(const void* __restrict__ ei) {
    const int* p = (const int*)ei;
    int ok64 = 1;
    #pragma unroll
    for (int i = 0; i < 32; ++i)
        if (p[2 * i + 1] != 0) ok64 = 0;
    g_is64 = ok64;
}

__global__ void k_zerodeg(int n) {
    int i = blockIdx.x * blockDim.x + threadIdx.x;
    if (i < n) g_degi[i] = 0;
}

// ---- decode edge_index -> int2 + integer degree histogram ----
__global__ void k_decode(const void* __restrict__ ei, int E) {
    int e = blockIdx.x * blockDim.x + threadIdx.x;
    if (e >= E) return;
    int src, dst;
    if (g_is64) {
        const long long* p = (const long long*)ei;
        src = (int)p[e]; dst = (int)p[E + e];
    } else {
        const int* p = (const int*)ei;
        src = p[e]; dst = p[E + e];
    }
    g_eidx[e] = make_int2(src, dst);
    atomicAdd(&g_degi[dst], 1);
}

// ---- exclusive prefix sum of degrees (single block, sequential chunks) ----
__global__ void k_scan(int n) {
    int tid = threadIdx.x, lane = tid & 31, wid = tid >> 5;
    __shared__ int wsum[32];
    int carry = 0;
    for (int base = 0; base < n; base += 1024) {
        int i = base + tid;
        int v = (i < n) ? g_degi[i] : 0;
        int s = v;
        #pragma unroll
        for (int d = 1; d < 32; d <<= 1) {
            int t = __shfl_up_sync(FULLMASK, s, d);
            if (lane >= d) s += t;
        }
        if (lane == 31) wsum[wid] = s;
        __syncthreads();
        if (wid == 0) {
            int ws = wsum[lane];
            #pragma unroll
            for (int d = 1; d < 32; d <<= 1) {
                int t = __shfl_up_sync(FULLMASK, ws, d);
                if (lane >= d) ws += t;
            }
            wsum[lane] = ws;
        }
        __syncthreads();
        int off = (wid > 0) ? wsum[wid - 1] : 0;
        int excl = carry + off + s - v;
        if (i < n) { g_rs[i] = excl; g_cur[i] = excl; }
        carry += wsum[31];
        __syncthreads();
    }
}

// ---- CSR placement: scatter (src, u) into dest-sorted slots ----
__global__ void k_place(const float* __restrict__ ea, int E) {
    int e = blockIdx.x * blockDim.x + threadIdx.x;
    if (e >= E) return;
    int2 sd = g_eidx[e];
    int pos = atomicAdd(&g_cur[sd.y], 1);
    g_csr[pos] = make_int2(sd.x, __float_as_int(ea[e]));
}

// ---- layer-1 node precompute: packed float4 weights, one LDS.128 per k ----
__global__ void k_prep1(const float* __restrict__ x,
                        const float* __restrict__ W1,     // (2,32,32)
                        const float* __restrict__ root1,  // (32,32)
                        const float* __restrict__ b1,
                        int n) {
    __shared__ float4 sP[1024];                           // {W0, W1-W0, root, 0}
    for (int i = threadIdx.x; i < 1024; i += blockDim.x) {
        float w0 = W1[i];
        sP[i] = make_float4(w0, W1[1024 + i] - w0, root1[i], 0.f);
    }
    __syncthreads();
    int lane = threadIdx.x & 31;
    int node = blockIdx.x * (blockDim.x >> 5) + (threadIdx.x >> 5);
    if (node >= n) return;
    float xv = x[node * 32 + lane];
    float a0 = 0.f, ad = 0.f, ar = 0.f;
    #pragma unroll
    for (int k = 0; k < 32; ++k) {
        float xk = __shfl_sync(FULLMASK, xv, k);
        float4 w = sP[k * 32 + lane];
        a0 = fmaf(xk, w.x, a0);
        ad = fmaf(xk, w.y, ad);
        ar = fmaf(xk, w.z, ar);
    }
    int o = node * 32 + lane;
    g_p1[o] = __floats2half2_rn(a0, ad);
    g_r1[o] = ar + b1[lane];
}

// ---- layer-1 gather-reduce + combine + fused layer-2 node precompute ----
// Warp per dest node, lane = feature. CSR entries loaded coalesced, shuffled out.
__global__ void k_gather1(const float* __restrict__ W2,     // (2,32,10)
                          const float* __restrict__ root2,  // (32,10)
                          const float* __restrict__ b2,
                          int n) {
    __shared__ float4 sP2[512];                           // [k*16+j] {W0, W1-W0, root, 0}
    __shared__ float  sB2[16];
    int tid = threadIdx.x;
    for (int i = tid; i < 512; i += blockDim.x) {
        int k = i >> 4, j = i & 15;
        float w0 = 0.f, wd = 0.f, r = 0.f;
        if (j < 10) {
            w0 = W2[k * 10 + j];
            wd = W2[320 + k * 10 + j] - w0;
            r  = root2[k * 10 + j];
        }
        sP2[i] = make_float4(w0, wd, r, 0.f);
    }
    if (tid < 16) sB2[tid] = (tid < 10) ? b2[tid] : 0.f;
    __syncthreads();
    int lane = tid & 31;
    int d = blockIdx.x * (blockDim.x >> 5) + (tid >> 5);
    if (d >= n) return;
    int deg = g_degi[d];
    int start = g_rs[d], end = start + deg;
    float acc = 0.f;
    for (int base = start; base < end; base += 32) {
        int p = base + lane;
        int2 e = (p < end) ? g_csr[p] : make_int2(0, 0);
        int cnt = end - base;
        #pragma unroll
        for (int j = 0; j < 32; ++j) {
            int   sj = __shfl_sync(FULLMASK, e.x, j);
            float uj = __int_as_float(__shfl_sync(FULLMASK, e.y, j));
            if (j < cnt) {
                float2 f = __half22float2(g_p1[sj * 32 + lane]);
                acc += fmaf(uj, f.y, f.x);
            }
        }
    }
    float inv = 1.0f / fmaxf((float)deg, 1.0f);
    float h = fmaxf(acc * inv + g_r1[d * 32 + lane], 0.0f);
    // fused prep2: full h row lives in the warp's registers
    int j2 = lane & 15;
    float a0 = 0.f, ad = 0.f, ar = 0.f;
    #pragma unroll
    for (int k = 0; k < 32; ++k) {
        float hk = __shfl_sync(FULLMASK, h, k);
        float4 w = sP2[k * 16 + j2];
        a0 = fmaf(hk, w.x, a0);
        ad = fmaf(hk, w.y, ad);
        ar = fmaf(hk, w.z, ar);
    }
    if (lane < 16) {
        int o = d * 16 + lane;
        g_p2[o] = __floats2half2_rn(a0, ad);
        g_r2[o] = ar + sB2[lane];
    }
}

// ---- layer-2 gather-reduce + mean + log_softmax. 16-lane group per node. ----
// NOTE: the two halves of a warp process DIFFERENT nodes with different CSR
// loop trip counts, so ALL shuffles here use the half-warp mask only.
__global__ void k_gather2(float* __restrict__ out, int n) {
    int tid = blockIdx.x * blockDim.x + threadIdx.x;
    int lane = threadIdx.x & 31;
    int half = lane >> 4;
    int sl = lane & 15;
    unsigned mask = half ? 0xFFFF0000u : 0x0000FFFFu;
    int d = tid >> 4;
    bool valid = (d < n);
    int deg   = valid ? g_degi[d] : 0;
    int start = valid ? g_rs[d] : 0;
    int end = start + deg;
    float acc = 0.f;
    for (int base = start; base < end; base += 16) {
        int p = base + sl;
        int2 e = (p < end) ? g_csr[p] : make_int2(0, 0);
        int cnt = end - base;
        #pragma unroll
        for (int j = 0; j < 16; ++j) {
            int   sj = __shfl_sync(mask, e.x, (half << 4) + j);
            float uj = __int_as_float(__shfl_sync(mask, e.y, (half << 4) + j));
            if (j < cnt) {
                float2 f = __half22float2(g_p2[sj * 16 + sl]);   // cols 10..15 zero
                acc += fmaf(uj, f.y, f.x);
            }
        }
    }
    float inv = 1.0f / fmaxf((float)deg, 1.0f);
    float z = valid ? (acc * inv + g_r2[d * 16 + sl]) : 0.f;
    float zm = (sl < 10) ? z : -1e30f;
    float m = zm;
    #pragma unroll
    for (int o = 8; o >= 1; o >>= 1) m = fmaxf(m, __shfl_xor_sync(mask, m, o));
    float ex = (sl < 10) ? __expf(z - m) : 0.f;
    float s = ex;
    #pragma unroll
    for (int o = 8; o >= 1; o >>= 1) s += __shfl_xor_sync(mask, s, o);
    float l = m + logf(s);
    if (valid && sl < 10) out[d * 10 + sl] = z - l;
}

extern "C" void kernel_launch(void* const* d_in, const int* in_sizes, int n_in,
                              void* d_out, int out_size) {
    const float* x     = (const float*)d_in[0];
    const void*  ei    = d_in[1];
    const float* ea    = (const float*)d_in[2];
    const float* W1    = (const float*)d_in[3];
    const float* root1 = (const float*)d_in[4];
    const float* b1    = (const float*)d_in[5];
    const float* W2    = (const float*)d_in[6];
    const float* root2 = (const float*)d_in[7];
    const float* b2    = (const float*)d_in[8];
    float* out = (float*)d_out;

    int N = in_sizes[0] / 32;
    int E = in_sizes[2];

    k_detect<<<1, 1>>>(ei);
    k_zerodeg<<<(N + 255) / 256, 256>>>(N);
    k_decode<<<(E + 255) / 256, 256>>>(ei, E);
    k_scan<<<1, 1024>>>(N);
    k_place<<<(E + 255) / 256, 256>>>(ea, E);
    k_prep1<<<(N + 7) / 8, 256>>>(x, W1, root1, b1, N);
    k_gather1<<<(N + 7) / 8, 256>>>(W2, root2, b2, N);
    {
        long long th = (long long)N * 16;
        k_gather2<<<(int)((th + 255) / 256), 256>>>(out, N);
    }
}

// round 5
// speedup vs baseline: 1.1186x; 1.1186x over previous
#include <cuda_runtime.h>
#include <cuda_fp16.h>

// splineGCN: 2-layer SplineConv (K=2), N=50000, E=1.6M, 32 -> 32 -> 10, log_softmax.
// CSR-by-destination, gather-reduce both layers. Dummy zero node at index N for
// branch-free gather tails. Block-atomic CSR slot allocation (no serial scan).

#define NMAX 50000
#define EMAX 1600000
#define FULLMASK 0xffffffffu

// ---- scratch (dummy node at row NMAX) ----
__device__ __half2 g_p1 [(NMAX + 1) * 32];  // packed {h0, h1-h0}
__device__ float   g_r1 [NMAX * 32];        // x @ root1 + b1
__device__ __half2 g_p2 [(NMAX + 1) * 16];  // packed {g0, g1-g0} (cols 10..15 zero)
__device__ float   g_r2 [NMAX * 16];
__device__ int     g_degi[NMAX];
__device__ int     g_rs [NMAX];
__device__ int     g_cur[NMAX];
__device__ int     g_total;
__device__ int2    g_eidx[EMAX];
__device__ int2    g_csr [EMAX];            // dest-sorted {src, float_bits(u)}
__device__ int     g_is64;

// ---- init: zero degrees/cursor/dummy rows + dtype detect ----
__global__ void k_init(const void* __restrict__ ei, int n) {
    int i = blockIdx.x * blockDim.x + threadIdx.x;
    if (i < n) g_degi[i] = 0;
    if (i == 0) {
        g_total = 0;
        const int* p = (const int*)ei;
        int ok64 = 1;
        #pragma unroll
        for (int k = 0; k < 32; ++k)
            if (p[2 * k + 1] != 0) ok64 = 0;
        g_is64 = ok64;
    }
    if (i < 32) g_p1[NMAX * 32 + i] = __floats2half2_rn(0.f, 0.f);
    if (i < 16) g_p2[NMAX * 16 + i] = __floats2half2_rn(0.f, 0.f);
}

// ---- fused: prep1 (blocks < PB) + decode (blocks >= PB) ----
__global__ void k_fused1(const float* __restrict__ x,
                         const float* __restrict__ W1,     // (2,32,32)
                         const float* __restrict__ root1,  // (32,32)
                         const float* __restrict__ b1,
                         const void* __restrict__ ei,
                         int n, int E, int PB) {
    if (blockIdx.x < PB) {
        // ---- layer-1 node precompute, warp per node ----
        __shared__ float4 sP[1024];                       // {W0, W1-W0, root, 0}
        for (int i = threadIdx.x; i < 1024; i += blockDim.x) {
            float w0 = W1[i];
            sP[i] = make_float4(w0, W1[1024 + i] - w0, root1[i], 0.f);
        }
        __syncthreads();
        int lane = threadIdx.x & 31;
        int node = blockIdx.x * (blockDim.x >> 5) + (threadIdx.x >> 5);
        if (node >= n) return;
        float xv = x[node * 32 + lane];
        float a0 = 0.f, ad = 0.f, ar = 0.f;
        #pragma unroll
        for (int k = 0; k < 32; ++k) {
            float xk = __shfl_sync(FULLMASK, xv, k);
            float4 w = sP[k * 32 + lane];
            a0 = fmaf(xk, w.x, a0);
            ad = fmaf(xk, w.y, ad);
            ar = fmaf(xk, w.z, ar);
        }
        int o = node * 32 + lane;
        g_p1[o] = __floats2half2_rn(a0, ad);
        g_r1[o] = ar + b1[lane];
    } else {
        // ---- decode edge_index -> int2 + degree histogram ----
        int e = (blockIdx.x - PB) * blockDim.x + threadIdx.x;
        if (e >= E) return;
        int src, dst;
        if (g_is64) {
            const long long* p = (const long long*)ei;
            src = (int)p[e]; dst = (int)p[E + e];
        } else {
            const int* p = (const int*)ei;
            src = p[e]; dst = p[E + e];
        }
        g_eidx[e] = make_int2(src, dst);
        atomicAdd(&g_degi[dst], 1);
    }
}

// ---- CSR range allocation: intra-block scan + one atomic per block ----
__global__ void k_alloc(int n) {
    int tid = threadIdx.x, lane = tid & 31, wid = tid >> 5;
    __shared__ int wsum[32];
    __shared__ int sBase;
    int i = blockIdx.x * 1024 + tid;
    int v = (i < n) ? g_degi[i] : 0;
    int s = v;
    #pragma unroll
    for (int d = 1; d < 32; d <<= 1) {
        int t = __shfl_up_sync(FULLMASK, s, d);
        if (lane >= d) s += t;
    }
    if (lane == 31) wsum[wid] = s;
    __syncthreads();
    if (wid == 0) {
        int ws = wsum[lane];
        #pragma unroll
        for (int d = 1; d < 32; d <<= 1) {
            int t = __shfl_up_sync(FULLMASK, ws, d);
            if (lane >= d) ws += t;
        }
        wsum[lane] = ws;
    }
    __syncthreads();
    int off = (wid > 0) ? wsum[wid - 1] : 0;
    int excl = off + s - v;
    if (tid == 1023) sBase = atomicAdd(&g_total, off + s);  // off+s == block total here
    __syncthreads();
    if (i < n) {
        int rs = sBase + excl;
        g_rs[i] = rs;
        g_cur[i] = rs;
    }
}

// ---- CSR placement ----
__global__ void k_place(const float* __restrict__ ea, int E) {
    int e = blockIdx.x * blockDim.x + threadIdx.x;
    if (e >= E) return;
    int2 sd = g_eidx[e];
    int pos = atomicAdd(&g_cur[sd.y], 1);
    g_csr[pos] = make_int2(sd.x, __float_as_int(ea[e]));
}

// ---- layer-1 gather-reduce + combine + fused layer-2 node precompute ----
// Warp per dest node, lane = feature. Branch-free inner loop via dummy node.
__global__ void k_gather1(const float* __restrict__ W2,     // (2,32,10)
                          const float* __restrict__ root2,  // (32,10)
                          const float* __restrict__ b2,
                          int n) {
    __shared__ float4 sP2[512];
    __shared__ float  sB2[16];
    int tid = threadIdx.x;
    for (int i = tid; i < 512; i += blockDim.x) {
        int k = i >> 4, j = i & 15;
        float w0 = 0.f, wd = 0.f, r = 0.f;
        if (j < 10) {
            w0 = W2[k * 10 + j];
            wd = W2[320 + k * 10 + j] - w0;
            r  = root2[k * 10 + j];
        }
        sP2[i] = make_float4(w0, wd, r, 0.f);
    }
    if (tid < 16) sB2[tid] = (tid < 10) ? b2[tid] : 0.f;
    __syncthreads();
    int lane = tid & 31;
    int d = blockIdx.x * (blockDim.x >> 5) + (tid >> 5);
    if (d >= n) return;
    int deg = g_degi[d];
    int start = g_rs[d], end = start + deg;
    float acc0 = 0.f, acc1 = 0.f;
    for (int base = start; base < end; base += 32) {
        int p = base + lane;
        int2 e = (p < end) ? g_csr[p] : make_int2(NMAX, 0);
        #pragma unroll
        for (int j = 0; j < 32; ++j) {
            int   sj = __shfl_sync(FULLMASK, e.x, j);
            float uj = __int_as_float(__shfl_sync(FULLMASK, e.y, j));
            float2 f = __half22float2(g_p1[sj * 32 + lane]);
            acc0 += f.x;
            acc1 = fmaf(uj, f.y, acc1);
        }
    }
    float inv = 1.0f / fmaxf((float)deg, 1.0f);
    float h = fmaxf((acc0 + acc1) * inv + g_r1[d * 32 + lane], 0.0f);
    // fused prep2
    int j2 = lane & 15;
    float a0 = 0.f, ad = 0.f, ar = 0.f;
    #pragma unroll
    for (int k = 0; k < 32; ++k) {
        float hk = __shfl_sync(FULLMASK, h, k);
        float4 w = sP2[k * 16 + j2];
        a0 = fmaf(hk, w.x, a0);
        ad = fmaf(hk, w.y, ad);
        ar = fmaf(hk, w.z, ar);
    }
    if (lane < 16) {
        int o = d * 16 + lane;
        g_p2[o] = __floats2half2_rn(a0, ad);
        g_r2[o] = ar + sB2[lane];
    }
}

// ---- layer-2 gather-reduce + mean + log_softmax. 16-lane group per node. ----
// Halves of a warp run different trip counts -> half-warp shuffle masks only.
__global__ void k_gather2(float* __restrict__ out, int n) {
    int tid = blockIdx.x * blockDim.x + threadIdx.x;
    int lane = threadIdx.x & 31;
    int half = lane >> 4;
    int sl = lane & 15;
    unsigned mask = half ? 0xFFFF0000u : 0x0000FFFFu;
    int d = tid >> 4;
    bool valid = (d < n);
    int deg   = valid ? g_degi[d] : 0;
    int start = valid ? g_rs[d] : 0;
    int end = start + deg;
    float acc0 = 0.f, acc1 = 0.f;
    for (int base = start; base < end; base += 16) {
        int p = base + sl;
        int2 e = (p < end) ? g_csr[p] : make_int2(NMAX, 0);
        #pragma unroll
        for (int j = 0; j < 16; ++j) {
            int   sj = __shfl_sync(mask, e.x, (half << 4) + j);
            float uj = __int_as_float(__shfl_sync(mask, e.y, (half << 4) + j));
            float2 f = __half22float2(g_p2[sj * 16 + sl]);
            acc0 += f.x;
            acc1 = fmaf(uj, f.y, acc1);
        }
    }
    float inv = 1.0f / fmaxf((float)deg, 1.0f);
    float z = valid ? ((acc0 + acc1) * inv + g_r2[d * 16 + sl]) : 0.f;
    float zm = (sl < 10) ? z : -1e30f;
    float m = zm;
    #pragma unroll
    for (int o = 8; o >= 1; o >>= 1) m = fmaxf(m, __shfl_xor_sync(mask, m, o));
    float ex = (sl < 10) ? __expf(z - m) : 0.f;
    float s = ex;
    #pragma unroll
    for (int o = 8; o >= 1; o >>= 1) s += __shfl_xor_sync(mask, s, o);
    float l = m + logf(s);
    if (valid && sl < 10) out[d * 10 + sl] = z - l;
}

extern "C" void kernel_launch(void* const* d_in, const int* in_sizes, int n_in,
                              void* d_out, int out_size) {
    const float* x     = (const float*)d_in[0];
    const void*  ei    = d_in[1];
    const float* ea    = (const float*)d_in[2];
    const float* W1    = (const float*)d_in[3];
    const float* root1 = (const float*)d_in[4];
    const float* b1    = (const float*)d_in[5];
    const float* W2    = (const float*)d_in[6];
    const float* root2 = (const float*)d_in[7];
    const float* b2    = (const float*)d_in[8];
    float* out = (float*)d_out;

    int N = in_sizes[0] / 32;
    int E = in_sizes[2];

    k_init<<<(N + 255) / 256, 256>>>(ei, N);
    int PB = (N + 7) / 8;               // prep1 blocks (8 warps of nodes each)
    int DB = (E + 255) / 256;           // decode blocks
    k_fused1<<<PB + DB, 256>>>(x, W1, root1, b1, ei, N, E, PB);
    k_alloc<<<(N + 1023) / 1024, 1024>>>(N);
    k_place<<<(E + 255) / 256, 256>>>(ea, E);
    k_gather1<<<(N + 7) / 8, 256>>>(W2, root2, b2, N);
    {
        long long th = (long long)N * 16;
        k_gather2<<<(int)((th + 255) / 256), 256>>>(out, N);
    }
}

// round 7
// speedup vs baseline: 1.2684x; 1.1339x over previous
#include <cuda_runtime.h>
#include <cuda_fp16.h>

// splineGCN: 2-layer SplineConv (K=2), N=50000, E=1.6M, 32 -> 32 -> 10, log_softmax.
// Atomic-RED scatter skeleton (measured fastest) + fused prep/combine kernels,
// fp16-packed message tables, float4-packed weight smem, branch-free edge tails.

#define NMAX 50000
#define EMAX 1600000
#define FULLMASK 0xffffffffu

// ---- scratch (dummy node/agg row at index NMAX) ----
__device__ __half2 g_p1  [(NMAX + 1) * 32];  // packed {h0, h1-h0}
__device__ float   g_r1  [NMAX * 32];        // x @ root1 + b1
__device__ float   g_agg1[(NMAX + 1) * 32];
__device__ __half2 g_p2  [(NMAX + 1) * 16];  // packed {g0, g1-g0} (cols 10..15 zero)
__device__ float   g_r2  [NMAX * 16];
__device__ float   g_agg2[(NMAX + 1) * 16];
__device__ int     g_degi[NMAX];
__device__ int2    g_eidx[EMAX];             // decoded (src, dst)
__device__ int     g_is64;

// ---- init: vectorized zeroing + dtype detect + dummy rows ----
__global__ void k_init(const void* __restrict__ ei, int n) {
    int i = blockIdx.x * blockDim.x + threadIdx.x;
    int n1 = (n + 1) * 8;     // agg1 float4 count
    int n2 = (n + 1) * 4;     // agg2 float4 count
    float4 z = make_float4(0.f, 0.f, 0.f, 0.f);
    if (i < n1) ((float4*)g_agg1)[i] = z;
    if (i < n2) ((float4*)g_agg2)[i] = z;
    if (i < (n + 3) / 4) ((int4*)g_degi)[i] = make_int4(0, 0, 0, 0);
    if (i < 32) g_p1[NMAX * 32 + i] = __floats2half2_rn(0.f, 0.f);
    if (i < 16) g_p2[NMAX * 16 + i] = __floats2half2_rn(0.f, 0.f);
    if (i == 0) {
        const int* p = (const int*)ei;
        int ok64 = 1;
        #pragma unroll
        for (int k = 0; k < 32; ++k)
            if (p[2 * k + 1] != 0) ok64 = 0;
        g_is64 = ok64;
    }
}

// ---- fused: prep1 (blocks < PB) + decode/degree (blocks >= PB) ----
__global__ void k_fused1(const float* __restrict__ x,
                         const float* __restrict__ W1,     // (2,32,32)
                         const float* __restrict__ root1,  // (32,32)
                         const float* __restrict__ b1,
                         const void* __restrict__ ei,
                         int n, int E, int PB) {
    if (blockIdx.x < PB) {
        __shared__ float4 sP[1024];                       // {W0, W1-W0, root, 0}
        for (int i = threadIdx.x; i < 1024; i += blockDim.x) {
            float w0 = W1[i];
            sP[i] = make_float4(w0, W1[1024 + i] - w0, root1[i], 0.f);
        }
        __syncthreads();
        int lane = threadIdx.x & 31;
        int node = blockIdx.x * (blockDim.x >> 5) + (threadIdx.x >> 5);
        if (node >= n) return;
        float xv = x[node * 32 + lane];
        float a0 = 0.f, ad = 0.f, ar = 0.f;
        #pragma unroll
        for (int k = 0; k < 32; ++k) {
            float xk = __shfl_sync(FULLMASK, xv, k);
            float4 w = sP[k * 32 + lane];
            a0 = fmaf(xk, w.x, a0);
            ad = fmaf(xk, w.y, ad);
            ar = fmaf(xk, w.z, ar);
        }
        int o = node * 32 + lane;
        g_p1[o] = __floats2half2_rn(a0, ad);
        g_r1[o] = ar + b1[lane];
    } else {
        int e = (blockIdx.x - PB) * blockDim.x + threadIdx.x;
        if (e >= E) return;
        int src, dst;
        if (g_is64) {
            const long long* p = (const long long*)ei;
            src = (int)p[e]; dst = (int)p[E + e];
        } else {
            const int* p = (const int*)ei;
            src = p[e]; dst = p[E + e];
        }
        g_eidx[e] = make_int2(src, dst);
        atomicAdd(&g_degi[dst], 1);
    }
}

// ---- layer-1 edge scatter: warp/4-edges, lane = feature, branch-free tail ----
#define EPW1 4
__global__ void k_edge1(const float* __restrict__ ea, int E) {
    int w = (blockIdx.x * blockDim.x + threadIdx.x) >> 5;
    int lane = threadIdx.x & 31;
    int e0 = w * EPW1;
    if (e0 >= E) return;
    int2  idx[EPW1];
    float u  [EPW1];
    #pragma unroll
    for (int i = 0; i < EPW1; ++i) {
        int e = e0 + i;
        if (e < E) { idx[i] = g_eidx[e]; u[i] = __ldg(&ea[e]); }
        else       { idx[i] = make_int2(NMAX, NMAX); u[i] = 0.f; }
    }
    float2 f[EPW1];
    #pragma unroll
    for (int i = 0; i < EPW1; ++i)
        f[i] = __half22float2(g_p1[idx[i].x * 32 + lane]);
    #pragma unroll
    for (int i = 0; i < EPW1; ++i)
        atomicAdd(&g_agg1[idx[i].y * 32 + lane], fmaf(u[i], f[i].y, f[i].x));
}

// ---- combine1 + fused layer-2 node precompute. Warp per node. ----
__global__ void k_gcomb1(const float* __restrict__ W2,     // (2,32,10)
                         const float* __restrict__ root2,  // (32,10)
                         const float* __restrict__ b2,
                         int n) {
    __shared__ float4 sP2[512];                           // [k*16+j] {W0, W1-W0, root, 0}
    __shared__ float  sB2[16];
    int tid = threadIdx.x;
    for (int i = tid; i < 512; i += blockDim.x) {
        int k = i >> 4, j = i & 15;
        float w0 = 0.f, wd = 0.f, r = 0.f;
        if (j < 10) {
            w0 = W2[k * 10 + j];
            wd = W2[320 + k * 10 + j] - w0;
            r  = root2[k * 10 + j];
        }
        sP2[i] = make_float4(w0, wd, r, 0.f);
    }
    if (tid < 16) sB2[tid] = (tid < 10) ? b2[tid] : 0.f;
    __syncthreads();
    int lane = tid & 31;
    int d = blockIdx.x * (blockDim.x >> 5) + (tid >> 5);
    if (d >= n) return;
    float inv = 1.0f / fmaxf((float)g_degi[d], 1.0f);
    float h = fmaxf(g_agg1[d * 32 + lane] * inv + g_r1[d * 32 + lane], 0.0f);
    int j2 = lane & 15;
    float a0 = 0.f, ad = 0.f, ar = 0.f;
    #pragma unroll
    for (int k = 0; k < 32; ++k) {
        float hk = __shfl_sync(FULLMASK, h, k);
        float4 w = sP2[k * 16 + j2];
        a0 = fmaf(hk, w.x, a0);
        ad = fmaf(hk, w.y, ad);
        ar = fmaf(hk, w.z, ar);
    }
    if (lane < 16) {
        int o = d * 16 + lane;
        g_p2[o] = __floats2half2_rn(a0, ad);
        g_r2[o] = ar + sB2[lane];
    }
}

// ---- layer-2 edge scatter: 16-lane sub-warp, 4 edges, branch-free ----
#define EPW2 4
__global__ void k_edge2(const float* __restrict__ ea, int E) {
    int tid = blockIdx.x * blockDim.x + threadIdx.x;
    int sw = tid >> 4;
    int sl = tid & 15;
    int e0 = sw * EPW2;
    if (e0 >= E) return;
    int2  idx[EPW2];
    float u  [EPW2];
    #pragma unroll
    for (int i = 0; i < EPW2; ++i) {
        int e = e0 + i;
        if (e < E) { idx[i] = g_eidx[e]; u[i] = __ldg(&ea[e]); }
        else       { idx[i] = make_int2(NMAX, NMAX); u[i] = 0.f; }
    }
    float2 f[EPW2];
    #pragma unroll
    for (int i = 0; i < EPW2; ++i)
        f[i] = __half22float2(g_p2[idx[i].x * 16 + sl]);   // cols 10..15 zero
    #pragma unroll
    for (int i = 0; i < EPW2; ++i)
        if (sl < 10)
            atomicAdd(&g_agg2[idx[i].y * 16 + sl], fmaf(u[i], f[i].y, f[i].x));
}

// ---- combine2 + log_softmax. 16-lane group per node, uniform control flow. ----
__global__ void k_comb2(float* __restrict__ out, int n) {
    int tid = blockIdx.x * blockDim.x + threadIdx.x;
    int lane = threadIdx.x & 31;
    int half = lane >> 4;
    int sl = lane & 15;
    unsigned mask = half ? 0xFFFF0000u : 0x0000FFFFu;
    int d = tid >> 4;
    bool valid = (d < n);
    float inv = valid ? (1.0f / fmaxf((float)g_degi[d], 1.0f)) : 1.0f;
    float z = valid ? (g_agg2[d * 16 + sl] * inv + g_r2[d * 16 + sl]) : 0.f;
    float zm = (sl < 10) ? z : -1e30f;
    float m = zm;
    #pragma unroll
    for (int o = 8; o >= 1; o >>= 1) m = fmaxf(m, __shfl_xor_sync(mask, m, o));
    float ex = (sl < 10) ? __expf(z - m) : 0.f;
    float s = ex;
    #pragma unroll
    for (int o = 8; o >= 1; o >>= 1) s += __shfl_xor_sync(mask, s, o);
    float l = m + logf(s);
    if (valid && sl < 10) out[d * 10 + sl] = z - l;
}

extern "C" void kernel_launch(void* const* d_in, const int* in_sizes, int n_in,
                              void* d_out, int out_size) {
    const float* x     = (const float*)d_in[0];
    const void*  ei    = d_in[1];
    const float* ea    = (const float*)d_in[2];
    const float* W1    = (const float*)d_in[3];
    const float* root1 = (const float*)d_in[4];
    const float* b1    = (const float*)d_in[5];
    const float* W2    = (const float*)d_in[6];
    const float* root2 = (const float*)d_in[7];
    const float* b2    = (const float*)d_in[8];
    float* out = (float*)d_out;

    int N = in_sizes[0] / 32;
    int E = in_sizes[2];

    {
        int zthreads = (N + 1) * 8;                       // agg1 float4 elems dominate
        k_init<<<(zthreads + 255) / 256, 256>>>(ei, N);
    }
    int PB = (N + 7) / 8;
    int DB = (E + 255) / 256;
    k_fused1<<<PB + DB, 256>>>(x, W1, root1, b1, ei, N, E, PB);
    {
        long long th = ((long long)(E + EPW1 - 1) / EPW1) * 32;
        k_edge1<<<(int)((th + 255) / 256), 256>>>(ea, E);
    }
    k_gcomb1<<<(N + 7) / 8, 256>>>(W2, root2, b2, N);
    {
        long long th = ((long long)(E + EPW2 - 1) / EPW2) * 16;
        k_edge2<<<(int)((th + 255) / 256), 256>>>(ea, E);
    }
    {
        long long th = (long long)N * 16;
        k_comb2<<<(int)((th + 255) / 256), 256>>>(out, N);
    }
}

// round 9
// speedup vs baseline: 1.6637x; 1.3116x over previous
#include <cuda_runtime.h>
#include <cuda_fp16.h>

// splineGCN: 2-layer SplineConv (K=2), N=50000, E=1.6M, 32 -> 32 -> 10, log_softmax.
// Atomic-RED skeleton + fp16-pair packed GEMMs, packed 4B edge metadata,
// fp16x2 RED aggregation. Branch-free edge tails via dummy node at NMAX.

#define NMAX 50000
#define EMAX 1600000
#define FULLMASK 0xffffffffu

// ---- scratch (dummy node/agg row at index NMAX) ----
__device__ __half2  g_p1  [(NMAX + 1) * 32];   // {h0, h1-h0} per (node, feat)
__device__ float    g_r1  [NMAX * 32];         // x @ root1 + b1
__device__ __half   g_agg1[(NMAX + 1) * 32];   // fp16 accumulators (RED.F16x2)
__device__ __half2  g_p2  [(NMAX + 1) * 16];   // {g0, g1-g0} (cols 10..15 zero)
__device__ float    g_r2  [NMAX * 16];
__device__ __half   g_agg2[(NMAX + 1) * 16];
__device__ int      g_degi[NMAX];
__device__ unsigned g_esd [EMAX];              // src | dst<<16
__device__ int      g_is64;

static __device__ __forceinline__ unsigned h2u(float a, float b) {
    __half2 h = __floats2half2_rn(a, b);
    return *reinterpret_cast<unsigned*>(&h);
}
static __device__ __forceinline__ float2 u2f2(unsigned v) {
    __half2 h = *reinterpret_cast<__half2*>(&v);
    return __half22float2(h);
}

// ---- init: vectorized zeroing + dtype detect + dummy rows ----
__global__ void k_init(const void* __restrict__ ei, int n) {
    int i = blockIdx.x * blockDim.x + threadIdx.x;
    float4 z = make_float4(0.f, 0.f, 0.f, 0.f);
    if (i < (n + 1) * 4) ((float4*)g_agg1)[i] = z;          // 32 halfs = 4 float4 / node
    if (i < (n + 1) * 2) ((float4*)g_agg2)[i] = z;          // 16 halfs = 2 float4 / node
    if (i < (n + 3) / 4) ((int4*)g_degi)[i] = make_int4(0, 0, 0, 0);
    if (i < 32) g_p1[NMAX * 32 + i] = __floats2half2_rn(0.f, 0.f);
    if (i < 16) g_p2[NMAX * 16 + i] = __floats2half2_rn(0.f, 0.f);
    if (i == 0) {
        const int* p = (const int*)ei;
        int ok64 = 1;
        #pragma unroll
        for (int k = 0; k < 32; ++k)
            if (p[2 * k + 1] != 0) ok64 = 0;
        g_is64 = ok64;
    }
}

// ---- fused: prep1 (blocks < PB) + decode/degree (blocks >= PB) ----
__global__ void k_fused1(const float* __restrict__ x,
                         const float* __restrict__ W1,     // (2,32,32)
                         const float* __restrict__ root1,  // (32,32)
                         const float* __restrict__ b1,
                         const void* __restrict__ ei,
                         int n, int E, int PB) {
    if (blockIdx.x < PB) {
        // fp16-pair packed weights: sPh[k*32+j] = {W0 pair, dW pair, root pair} for
        // features (2k, 2k+1) -> output column j.
        __shared__ uint4 sPh[512];
        for (int i = threadIdx.x; i < 512; i += blockDim.x) {
            int k = i >> 5, j = i & 31;
            float w0a = W1[(2 * k) * 32 + j],     w0b = W1[(2 * k + 1) * 32 + j];
            float w1a = W1[1024 + (2 * k) * 32 + j], w1b = W1[1024 + (2 * k + 1) * 32 + j];
            float ra  = root1[(2 * k) * 32 + j],  rb  = root1[(2 * k + 1) * 32 + j];
            sPh[i] = make_uint4(h2u(w0a, w0b), h2u(w1a - w0a, w1b - w0b), h2u(ra, rb), 0u);
        }
        __syncthreads();
        int lane = threadIdx.x & 31;
        int node = blockIdx.x * (blockDim.x >> 5) + (threadIdx.x >> 5);
        if (node >= n) return;
        unsigned xpack = 0;
        {
            int j = lane & 15;
            float2 xp = ((const float2*)(x + node * 32))[j];
            xpack = h2u(xp.x, xp.y);
        }
        float a0 = 0.f, ad = 0.f, ar = 0.f;
        #pragma unroll
        for (int k = 0; k < 16; ++k) {
            unsigned xk = __shfl_sync(FULLMASK, xpack, k);
            float2 hx = u2f2(xk);
            uint4 w = sPh[k * 32 + lane];
            float2 w0 = u2f2(w.x), wd = u2f2(w.y), wr = u2f2(w.z);
            a0 = fmaf(hx.y, w0.y, fmaf(hx.x, w0.x, a0));
            ad = fmaf(hx.y, wd.y, fmaf(hx.x, wd.x, ad));
            ar = fmaf(hx.y, wr.y, fmaf(hx.x, wr.x, ar));
        }
        int o = node * 32 + lane;
        g_p1[o] = __floats2half2_rn(a0, ad);
        g_r1[o] = ar + b1[lane];
    } else {
        int e = (blockIdx.x - PB) * blockDim.x + threadIdx.x;
        if (e >= E) return;
        int src, dst;
        if (g_is64) {
            const long long* p = (const long long*)ei;
            src = (int)p[e]; dst = (int)p[E + e];
        } else {
            const int* p = (const int*)ei;
            src = p[e]; dst = p[E + e];
        }
        g_esd[e] = (unsigned)src | ((unsigned)dst << 16);
        atomicAdd(&g_degi[dst], 1);
    }
}

// ---- layer-1 edge scatter: 16-lane sub-warp, lane owns feature PAIR ----
#define EPW1 4
__global__ void k_edge1(const float* __restrict__ ea, int E) {
    int tid = blockIdx.x * blockDim.x + threadIdx.x;
    int sw = tid >> 4;
    int sl = tid & 15;
    int e0 = sw * EPW1;
    if (e0 >= E) return;
    unsigned sd[EPW1];
    float    u [EPW1];
    #pragma unroll
    for (int i = 0; i < EPW1; ++i) {
        int e = e0 + i;
        if (e < E) { sd[i] = g_esd[e]; u[i] = __ldg(&ea[e]); }
        else       { sd[i] = (unsigned)NMAX | ((unsigned)NMAX << 16); u[i] = 0.f; }
    }
    uint2 v[EPW1];
    #pragma unroll
    for (int i = 0; i < EPW1; ++i)
        v[i] = ((const uint2*)g_p1)[(sd[i] & 0xFFFFu) * 16 + sl];
    #pragma unroll
    for (int i = 0; i < EPW1; ++i) {
        float2 fa = u2f2(v[i].x), fb = u2f2(v[i].y);
        float m0 = fmaf(u[i], fa.y, fa.x);
        float m1 = fmaf(u[i], fb.y, fb.x);
        __half2 mh = __floats2half2_rn(m0, m1);
        atomicAdd(((__half2*)g_agg1) + (sd[i] >> 16) * 16 + sl, mh);
    }
}

// ---- combine1 + fused layer-2 node precompute. Warp per node. ----
__global__ void k_gcomb1(const float* __restrict__ W2,     // (2,32,10)
                         const float* __restrict__ root2,  // (32,10)
                         const float* __restrict__ b2,
                         int n) {
    __shared__ uint4 sP2h[256];   // [k*16+j] {W0 pair, dW pair, root pair} fp16
    __shared__ float sB2[16];
    int tid = threadIdx.x;
    for (int i = tid; i < 256; i += blockDim.x) {
        int k = i >> 4, j = i & 15;
        float w0a = 0.f, w0b = 0.f, wda = 0.f, wdb = 0.f, ra = 0.f, rb = 0.f;
        if (j < 10) {
            w0a = W2[(2 * k) * 10 + j];       w0b = W2[(2 * k + 1) * 10 + j];
            wda = W2[320 + (2 * k) * 10 + j] - w0a;
            wdb = W2[320 + (2 * k + 1) * 10 + j] - w0b;
            ra  = root2[(2 * k) * 10 + j];    rb  = root2[(2 * k + 1) * 10 + j];
        }
        sP2h[i] = make_uint4(h2u(w0a, w0b), h2u(wda, wdb), h2u(ra, rb), 0u);
    }
    if (tid < 16) sB2[tid] = (tid < 10) ? ((const float*)b2)[tid] : 0.f;
    __syncthreads();
    int lane = tid & 31;
    int d = blockIdx.x * (blockDim.x >> 5) + (tid >> 5);
    if (d >= n) return;
    float inv = 1.0f / fmaxf((float)g_degi[d], 1.0f);
    float agg = __half2float(g_agg1[d * 32 + lane]);
    float h = fmaxf(agg * inv + g_r1[d * 32 + lane], 0.0f);
    // pack h pairs for half2 shuffle-GEMM
    int jp = lane & 15;
    unsigned hpack = h2u(__shfl_sync(FULLMASK, h, 2 * jp),
                         __shfl_sync(FULLMASK, h, 2 * jp + 1));
    int j2 = lane & 15;
    float a0 = 0.f, ad = 0.f, ar = 0.f;
    #pragma unroll
    for (int k = 0; k < 16; ++k) {
        unsigned hk = __shfl_sync(FULLMASK, hpack, k);
        float2 hx = u2f2(hk);
        uint4 w = sP2h[k * 16 + j2];
        float2 w0 = u2f2(w.x), wd = u2f2(w.y), wr = u2f2(w.z);
        a0 = fmaf(hx.y, w0.y, fmaf(hx.x, w0.x, a0));
        ad = fmaf(hx.y, wd.y, fmaf(hx.x, wd.x, ad));
        ar = fmaf(hx.y, wr.y, fmaf(hx.x, wr.x, ar));
    }
    if (lane < 16) {
        int o = d * 16 + lane;
        g_p2[o] = __floats2half2_rn(a0, ad);
        g_r2[o] = ar + sB2[lane];
    }
}

// ---- layer-2 edge scatter: 8-lane group, lane owns feature PAIR ----
#define EPW2 4
__global__ void k_edge2(const float* __restrict__ ea, int E) {
    int tid = blockIdx.x * blockDim.x + threadIdx.x;
    int grp = tid >> 3;
    int sl = tid & 7;
    int e0 = grp * EPW2;
    if (e0 >= E) return;
    unsigned sd[EPW2];
    float    u [EPW2];
    #pragma unroll
    for (int i = 0; i < EPW2; ++i) {
        int e = e0 + i;
        if (e < E) { sd[i] = g_esd[e]; u[i] = __ldg(&ea[e]); }
        else       { sd[i] = (unsigned)NMAX | ((unsigned)NMAX << 16); u[i] = 0.f; }
    }
    uint2 v[EPW2];
    #pragma unroll
    for (int i = 0; i < EPW2; ++i)
        v[i] = ((const uint2*)g_p2)[(sd[i] & 0xFFFFu) * 8 + sl];
    #pragma unroll
    for (int i = 0; i < EPW2; ++i) {
        if (sl < 5) {   // features 0..9 only (10..15 are zero columns)
            float2 fa = u2f2(v[i].x), fb = u2f2(v[i].y);
            float m0 = fmaf(u[i], fa.y, fa.x);
            float m1 = fmaf(u[i], fb.y, fb.x);
            __half2 mh = __floats2half2_rn(m0, m1);
            atomicAdd(((__half2*)g_agg2) + (sd[i] >> 16) * 8 + sl, mh);
        }
    }
}

// ---- combine2 + log_softmax. 16-lane group per node, half-warp masks. ----
__global__ void k_comb2(float* __restrict__ out, int n) {
    int tid = blockIdx.x * blockDim.x + threadIdx.x;
    int lane = threadIdx.x & 31;
    int half = lane >> 4;
    int sl = lane & 15;
    unsigned mask = half ? 0xFFFF0000u : 0x0000FFFFu;
    int d = tid >> 4;
    bool valid = (d < n);
    float inv = valid ? (1.0f / fmaxf((float)g_degi[d], 1.0f)) : 1.0f;
    float agg = valid ? __half2float(g_agg2[d * 16 + sl]) : 0.f;
    float z = valid ? (agg * inv + g_r2[d * 16 + sl]) : 0.f;
    float zm = (sl < 10) ? z : -1e30f;
    float m = zm;
    #pragma unroll
    for (int o = 8; o >= 1; o >>= 1) m = fmaxf(m, __shfl_xor_sync(mask, m, o));
    float ex = (sl < 10) ? __expf(z - m) : 0.f;
    float s = ex;
    #pragma unroll
    for (int o = 8; o >= 1; o >>= 1) s += __shfl_xor_sync(mask, s, o);
    float l = m + logf(s);
    if (valid && sl < 10) out[d * 10 + sl] = z - l;
}

extern "C" void kernel_launch(void* const* d_in, const int* in_sizes, int n_in,
                              void* d_out, int out_size) {
    const float* x     = (const float*)d_in[0];
    const void*  ei    = d_in[1];
    const float* ea    = (const float*)d_in[2];
    const float* W1    = (const float*)d_in[3];
    const float* root1 = (const float*)d_in[4];
    const float* b1    = (const float*)d_in[5];
    const float* W2    = (const float*)d_in[6];
    const float* root2 = (const float*)d_in[7];
    const float* b2    = (const float*)d_in[8];
    float* out = (float*)d_out;

    int N = in_sizes[0] / 32;
    int E = in_sizes[2];

    {
        int zthreads = (N + 1) * 4;                       // agg1 float4 elems dominate
        k_init<<<(zthreads + 255) / 256, 256>>>(ei, N);
    }
    int PB = (N + 7) / 8;
    int DB = (E + 255) / 256;
    k_fused1<<<PB + DB, 256>>>(x, W1, root1, b1, ei, N, E, PB);
    {
        long long th = ((long long)(E + EPW1 - 1) / EPW1) * 16;
        k_edge1<<<(int)((th + 255) / 256), 256>>>(ea, E);
    }
    k_gcomb1<<<(N + 7) / 8, 256>>>(W2, root2, b2, N);
    {
        long long th = ((long long)(E + EPW2 - 1) / EPW2) * 8;
        k_edge2<<<(int)((th + 255) / 256), 256>>>(ea, E);
    }
    {
        long long th = (long long)N * 16;
        k_comb2<<<(int)((th + 255) / 256), 256>>>(out, N);
    }
}

// round 12
// speedup vs baseline: 1.7628x; 1.0596x over previous
#include <cuda_runtime.h>
#include <cuda_fp16.h>

// splineGCN: 2-layer SplineConv (K=2), N=50000, E=1.6M, 32 -> 32 -> 10, log_softmax.
// Atomic-RED skeleton + fp16-pair packed GEMMs, packed 4B edge metadata,
// fp16x2 RED aggregation. gcomb1 uses split-k across warp halves (the 16-col
// GEMM was previously computed redundantly by both halves).

#define NMAX 50000
#define EMAX 1600000
#define FULLMASK 0xffffffffu

// ---- scratch (dummy node/agg row at index NMAX) ----
__device__ __half2  g_p1  [(NMAX + 1) * 32];   // {h0, h1-h0} per (node, feat)
__device__ float    g_r1  [NMAX * 32];         // x @ root1 + b1
__device__ __half   g_agg1[(NMAX + 1) * 32];   // fp16 accumulators (RED.F16x2)
__device__ __half2  g_p2  [(NMAX + 1) * 16];   // {g0, g1-g0} (cols 10..15 zero)
__device__ float    g_r2  [NMAX * 16];
__device__ __half   g_agg2[(NMAX + 1) * 16];
__device__ int      g_degi[NMAX];
__device__ unsigned g_esd [EMAX];              // src | dst<<16
__device__ int      g_is64;

static __device__ __forceinline__ unsigned h2u(float a, float b) {
    __half2 h = __floats2half2_rn(a, b);
    return *reinterpret_cast<unsigned*>(&h);
}
static __device__ __forceinline__ float2 u2f2(unsigned v) {
    __half2 h = *reinterpret_cast<__half2*>(&v);
    return __half22float2(h);
}

// ---- init: vectorized zeroing + dtype detect + dummy rows ----
__global__ void k_init(const void* __restrict__ ei, int n) {
    int i = blockIdx.x * blockDim.x + threadIdx.x;
    float4 z = make_float4(0.f, 0.f, 0.f, 0.f);
    if (i < (n + 1) * 4) ((float4*)g_agg1)[i] = z;          // 32 halfs = 4 float4 / node
    if (i < (n + 1) * 2) ((float4*)g_agg2)[i] = z;          // 16 halfs = 2 float4 / node
    if (i < (n + 3) / 4) ((int4*)g_degi)[i] = make_int4(0, 0, 0, 0);
    if (i < 32) g_p1[NMAX * 32 + i] = __floats2half2_rn(0.f, 0.f);
    if (i < 16) g_p2[NMAX * 16 + i] = __floats2half2_rn(0.f, 0.f);
    if (i == 0) {
        const int* p = (const int*)ei;
        int ok64 = 1;
        #pragma unroll
        for (int k = 0; k < 32; ++k)
            if (p[2 * k + 1] != 0) ok64 = 0;
        g_is64 = ok64;
    }
}

// ---- fused: prep1 (blocks < PB) + decode/degree (blocks >= PB) ----
__global__ void k_fused1(const float* __restrict__ x,
                         const float* __restrict__ W1,     // (2,32,32)
                         const float* __restrict__ root1,  // (32,32)
                         const float* __restrict__ b1,
                         const void* __restrict__ ei,
                         int n, int E, int PB) {
    if (blockIdx.x < PB) {
        // fp16-pair packed weights: sPh[k*32+j] = {W0 pair, dW pair, root pair} for
        // features (2k, 2k+1) -> output column j.
        __shared__ uint4 sPh[512];
        for (int i = threadIdx.x; i < 512; i += blockDim.x) {
            int k = i >> 5, j = i & 31;
            float w0a = W1[(2 * k) * 32 + j],     w0b = W1[(2 * k + 1) * 32 + j];
            float w1a = W1[1024 + (2 * k) * 32 + j], w1b = W1[1024 + (2 * k + 1) * 32 + j];
            float ra  = root1[(2 * k) * 32 + j],  rb  = root1[(2 * k + 1) * 32 + j];
            sPh[i] = make_uint4(h2u(w0a, w0b), h2u(w1a - w0a, w1b - w0b), h2u(ra, rb), 0u);
        }
        __syncthreads();
        int lane = threadIdx.x & 31;
        int node = blockIdx.x * (blockDim.x >> 5) + (threadIdx.x >> 5);
        if (node >= n) return;
        unsigned xpack = 0;
        {
            int j = lane & 15;
            float2 xp = ((const float2*)(x + node * 32))[j];
            xpack = h2u(xp.x, xp.y);
        }
        float a0 = 0.f, ad = 0.f, ar = 0.f;
        #pragma unroll
        for (int k = 0; k < 16; ++k) {
            unsigned xk = __shfl_sync(FULLMASK, xpack, k);
            float2 hx = u2f2(xk);
            uint4 w = sPh[k * 32 + lane];
            float2 w0 = u2f2(w.x), wd = u2f2(w.y), wr = u2f2(w.z);
            a0 = fmaf(hx.y, w0.y, fmaf(hx.x, w0.x, a0));
            ad = fmaf(hx.y, wd.y, fmaf(hx.x, wd.x, ad));
            ar = fmaf(hx.y, wr.y, fmaf(hx.x, wr.x, ar));
        }
        int o = node * 32 + lane;
        g_p1[o] = __floats2half2_rn(a0, ad);
        g_r1[o] = ar + b1[lane];
    } else {
        int e = (blockIdx.x - PB) * blockDim.x + threadIdx.x;
        if (e >= E) return;
        int src, dst;
        if (g_is64) {
            const long long* p = (const long long*)ei;
            src = (int)p[e]; dst = (int)p[E + e];
        } else {
            const int* p = (const int*)ei;
            src = p[e]; dst = p[E + e];
        }
        g_esd[e] = (unsigned)src | ((unsigned)dst << 16);
        atomicAdd(&g_degi[dst], 1);
    }
}

// ---- layer-1 edge scatter: 16-lane sub-warp, lane owns feature PAIR ----
#define EPW1 4
__global__ void k_edge1(const float* __restrict__ ea, int E) {
    int tid = blockIdx.x * blockDim.x + threadIdx.x;
    int sw = tid >> 4;
    int sl = tid & 15;
    int e0 = sw * EPW1;
    if (e0 >= E) return;
    unsigned sd[EPW1];
    float    u [EPW1];
    #pragma unroll
    for (int i = 0; i < EPW1; ++i) {
        int e = e0 + i;
        if (e < E) { sd[i] = g_esd[e]; u[i] = __ldg(&ea[e]); }
        else       { sd[i] = (unsigned)NMAX | ((unsigned)NMAX << 16); u[i] = 0.f; }
    }
    uint2 v[EPW1];
    #pragma unroll
    for (int i = 0; i < EPW1; ++i)
        v[i] = ((const uint2*)g_p1)[(sd[i] & 0xFFFFu) * 16 + sl];
    #pragma unroll
    for (int i = 0; i < EPW1; ++i) {
        float2 fa = u2f2(v[i].x), fb = u2f2(v[i].y);
        float m0 = fmaf(u[i], fa.y, fa.x);
        float m1 = fmaf(u[i], fb.y, fb.x);
        __half2 mh = __floats2half2_rn(m0, m1);
        atomicAdd(((__half2*)g_agg1) + (sd[i] >> 16) * 16 + sl, mh);
    }
}

// ---- combine1 + fused layer-2 node precompute. Warp per node. ----
// Split-k: lanes 0-15 accumulate k=0..7, lanes 16-31 accumulate k=8..15,
// then combine via shfl_xor(.,16). Removes the redundant duplicate GEMM.
__global__ void k_gcomb1(const float* __restrict__ W2,     // (2,32,10)
                         const float* __restrict__ root2,  // (32,10)
                         const float* __restrict__ b2,
                         int n) {
    __shared__ uint4 sP2h[256];   // [k*16+j] {W0 pair, dW pair, root pair} fp16
    __shared__ float sB2[16];
    int tid = threadIdx.x;
    for (int i = tid; i < 256; i += blockDim.x) {
        int k = i >> 4, j = i & 15;
        float w0a = 0.f, w0b = 0.f, wda = 0.f, wdb = 0.f, ra = 0.f, rb = 0.f;
        if (j < 10) {
            w0a = W2[(2 * k) * 10 + j];       w0b = W2[(2 * k + 1) * 10 + j];
            wda = W2[320 + (2 * k) * 10 + j] - w0a;
            wdb = W2[320 + (2 * k + 1) * 10 + j] - w0b;
            ra  = root2[(2 * k) * 10 + j];    rb  = root2[(2 * k + 1) * 10 + j];
        }
        sP2h[i] = make_uint4(h2u(w0a, w0b), h2u(wda, wdb), h2u(ra, rb), 0u);
    }
    if (tid < 16) sB2[tid] = (tid < 10) ? ((const float*)b2)[tid] : 0.f;
    __syncthreads();
    int lane = tid & 31;
    int d = blockIdx.x * (blockDim.x >> 5) + (tid >> 5);
    if (d >= n) return;
    float inv = 1.0f / fmaxf((float)g_degi[d], 1.0f);
    float agg = __half2float(g_agg1[d * 32 + lane]);
    float h = fmaxf(agg * inv + g_r1[d * 32 + lane], 0.0f);
    // pack h pairs for half2 shuffle-GEMM (lanes 0-15 hold valid pairs)
    int jp = lane & 15;
    unsigned hpack = h2u(__shfl_sync(FULLMASK, h, 2 * jp),
                         __shfl_sync(FULLMASK, h, 2 * jp + 1));
    int j2 = lane & 15;
    int kbase = (lane >> 4) << 3;       // 0 for lanes 0-15, 8 for lanes 16-31
    float a0 = 0.f, ad = 0.f, ar = 0.f;
    #pragma unroll
    for (int kk = 0; kk < 8; ++kk) {
        int k = kbase + kk;
        unsigned hk = __shfl_sync(FULLMASK, hpack, k);   // source lanes 0-15 only
        float2 hx = u2f2(hk);
        uint4 w = sP2h[k * 16 + j2];
        float2 w0 = u2f2(w.x), wd = u2f2(w.y), wr = u2f2(w.z);
        a0 = fmaf(hx.y, w0.y, fmaf(hx.x, w0.x, a0));
        ad = fmaf(hx.y, wd.y, fmaf(hx.x, wd.x, ad));
        ar = fmaf(hx.y, wr.y, fmaf(hx.x, wr.x, ar));
    }
    a0 += __shfl_xor_sync(FULLMASK, a0, 16);
    ad += __shfl_xor_sync(FULLMASK, ad, 16);
    ar += __shfl_xor_sync(FULLMASK, ar, 16);
    if (lane < 16) {
        int o = d * 16 + lane;
        g_p2[o] = __floats2half2_rn(a0, ad);
        g_r2[o] = ar + sB2[lane];
    }
}

// ---- layer-2 edge scatter: 8-lane group, lane owns feature PAIR ----
#define EPW2 4
__global__ void k_edge2(const float* __restrict__ ea, int E) {
    int tid = blockIdx.x * blockDim.x + threadIdx.x;
    int grp = tid >> 3;
    int sl = tid & 7;
    int e0 = grp * EPW2;
    if (e0 >= E) return;
    unsigned sd[EPW2];
    float    u [EPW2];
    #pragma unroll
    for (int i = 0; i < EPW2; ++i) {
        int e = e0 + i;
        if (e < E) { sd[i] = g_esd[e]; u[i] = __ldg(&ea[e]); }
        else       { sd[i] = (unsigned)NMAX | ((unsigned)NMAX << 16); u[i] = 0.f; }
    }
    uint2 v[EPW2];
    #pragma unroll
    for (int i = 0; i < EPW2; ++i)
        v[i] = ((const uint2*)g_p2)[(sd[i] & 0xFFFFu) * 8 + sl];
    #pragma unroll
    for (int i = 0; i < EPW2; ++i) {
        if (sl < 5) {   // features 0..9 only (10..15 are zero columns)
            float2 fa = u2f2(v[i].x), fb = u2f2(v[i].y);
            float m0 = fmaf(u[i], fa.y, fa.x);
            float m1 = fmaf(u[i], fb.y, fb.x);
            __half2 mh = __floats2half2_rn(m0, m1);
            atomicAdd(((__half2*)g_agg2) + (sd[i] >> 16) * 8 + sl, mh);
        }
    }
}

// ---- combine2 + log_softmax. 16-lane group per node, half-warp masks. ----
__global__ void k_comb2(float* __restrict__ out, int n) {
    int tid = blockIdx.x * blockDim.x + threadIdx.x;
    int lane = threadIdx.x & 31;
    int half = lane >> 4;
    int sl = lane & 15;
    unsigned mask = half ? 0xFFFF0000u : 0x0000FFFFu;
    int d = tid >> 4;
    bool valid = (d < n);
    float inv = valid ? (1.0f / fmaxf((float)g_degi[d], 1.0f)) : 1.0f;
    float agg = valid ? __half2float(g_agg2[d * 16 + sl]) : 0.f;
    float z = valid ? (agg * inv + g_r2[d * 16 + sl]) : 0.f;
    float zm = (sl < 10) ? z : -1e30f;
    float m = zm;
    #pragma unroll
    for (int o = 8; o >= 1; o >>= 1) m = fmaxf(m, __shfl_xor_sync(mask, m, o));
    float ex = (sl < 10) ? __expf(z - m) : 0.f;
    float s = ex;
    #pragma unroll
    for (int o = 8; o >= 1; o >>= 1) s += __shfl_xor_sync(mask, s, o);
    float l = m + logf(s);
    if (valid && sl < 10) out[d * 10 + sl] = z - l;
}

extern "C" void kernel_launch(void* const* d_in, const int* in_sizes, int n_in,
                              void* d_out, int out_size) {
    const float* x     = (const float*)d_in[0];
    const void*  ei    = d_in[1];
    const float* ea    = (const float*)d_in[2];
    const float* W1    = (const float*)d_in[3];
    const float* root1 = (const float*)d_in[4];
    const float* b1    = (const float*)d_in[5];
    const float* W2    = (const float*)d_in[6];
    const float* root2 = (const float*)d_in[7];
    const float* b2    = (const float*)d_in[8];
    float* out = (float*)d_out;

    int N = in_sizes[0] / 32;
    int E = in_sizes[2];

    {
        int zthreads = (N + 1) * 4;                       // agg1 float4 elems dominate
        k_init<<<(zthreads + 255) / 256, 256>>>(ei, N);
    }
    int PB = (N + 7) / 8;
    int DB = (E + 255) / 256;
    k_fused1<<<PB + DB, 256>>>(x, W1, root1, b1, ei, N, E, PB);
    {
        long long th = ((long long)(E + EPW1 - 1) / EPW1) * 16;
        k_edge1<<<(int)((th + 255) / 256), 256>>>(ea, E);
    }
    k_gcomb1<<<(N + 7) / 8, 256>>>(W2, root2, b2, N);
    {
        long long th = ((long long)(E + EPW2 - 1) / EPW2) * 8;
        k_edge2<<<(int)((th + 255) / 256), 256>>>(ea, E);
    }
    {
        long long th = (long long)N * 16;
        k_comb2<<<(int)((th + 255) / 256), 256>>>(out, N);
    }
}

// round 14
// speedup vs baseline: 1.8572x; 1.0536x over previous
#include <cuda_runtime.h>
#include <cuda_fp16.h>

// splineGCN: 2-layer SplineConv (K=2), N=50000, E=1.6M, 32 -> 32 -> 10, log_softmax.
// Atomic-RED skeleton; HFMA2 fp16-pair GEMMs (fp32 root path); planar-pair
// p1/p2 tables so the edge message is a single HFMA2; fp16x2 RED aggregation.

#define NMAX 50000
#define EMAX 1600000
#define FULLMASK 0xffffffffu

// ---- scratch (dummy node/agg row at index NMAX) ----
__device__ uint2    g_p1  [(NMAX + 1) * 16];   // {h0pair, hdpair} per (node, feat-pair)
__device__ float    g_r1  [NMAX * 32];         // x @ root1 + b1
__device__ __half   g_agg1[(NMAX + 1) * 32];   // fp16 accumulators (RED.F16x2)
__device__ uint2    g_p2  [(NMAX + 1) * 8];    // {g0pair, gdpair} (cols 10..15 zero)
__device__ float    g_r2  [NMAX * 16];
__device__ __half   g_agg2[(NMAX + 1) * 16];
__device__ int      g_degi[NMAX];
__device__ unsigned g_esd [EMAX];              // src | dst<<16
__device__ int      g_is64;

static __device__ __forceinline__ unsigned h2u(float a, float b) {
    __half2 h = __floats2half2_rn(a, b);
    return *reinterpret_cast<unsigned*>(&h);
}
static __device__ __forceinline__ float2 u2f2(unsigned v) {
    __half2 h = *reinterpret_cast<__half2*>(&v);
    return __half22float2(h);
}
static __device__ __forceinline__ __half2 u2h2(unsigned v) {
    return *reinterpret_cast<__half2*>(&v);
}

// ---- init: vectorized zeroing + dtype detect + dummy rows ----
__global__ void k_init(const void* __restrict__ ei, int n) {
    int i = blockIdx.x * blockDim.x + threadIdx.x;
    float4 z = make_float4(0.f, 0.f, 0.f, 0.f);
    if (i < (n + 1) * 4) ((float4*)g_agg1)[i] = z;          // 32 halfs = 4 float4 / node
    if (i < (n + 1) * 2) ((float4*)g_agg2)[i] = z;          // 16 halfs = 2 float4 / node
    if (i < (n + 3) / 4) ((int4*)g_degi)[i] = make_int4(0, 0, 0, 0);
    if (i < 16) g_p1[NMAX * 16 + i] = make_uint2(0u, 0u);
    if (i < 8)  g_p2[NMAX * 8 + i]  = make_uint2(0u, 0u);
    if (i == 0) {
        const int* p = (const int*)ei;
        int ok64 = 1;
        #pragma unroll
        for (int k = 0; k < 32; ++k)
            if (p[2 * k + 1] != 0) ok64 = 0;
        g_is64 = ok64;
    }
}

// ---- fused: prep1 (blocks < PB) + decode/degree (blocks >= PB) ----
__global__ void k_fused1(const float* __restrict__ x,
                         const float* __restrict__ W1,     // (2,32,32)
                         const float* __restrict__ root1,  // (32,32)
                         const float* __restrict__ b1,
                         const void* __restrict__ ei,
                         int n, int E, int PB) {
    if (blockIdx.x < PB) {
        // sPh[k*32+j] = {W0 pair, dW pair, root pair} fp16 for features (2k,2k+1) -> col j
        __shared__ uint4 sPh[512];
        for (int i = threadIdx.x; i < 512; i += blockDim.x) {
            int k = i >> 5, j = i & 31;
            float w0a = W1[(2 * k) * 32 + j],     w0b = W1[(2 * k + 1) * 32 + j];
            float w1a = W1[1024 + (2 * k) * 32 + j], w1b = W1[1024 + (2 * k + 1) * 32 + j];
            float ra  = root1[(2 * k) * 32 + j],  rb  = root1[(2 * k + 1) * 32 + j];
            sPh[i] = make_uint4(h2u(w0a, w0b), h2u(w1a - w0a, w1b - w0b), h2u(ra, rb), 0u);
        }
        __syncthreads();
        int lane = threadIdx.x & 31;
        int node = blockIdx.x * (blockDim.x >> 5) + (threadIdx.x >> 5);
        if (node >= n) return;
        unsigned xpack = 0;
        {
            int j = lane & 15;
            float2 xp = ((const float2*)(x + node * 32))[j];
            xpack = h2u(xp.x, xp.y);
        }
        __half2 acc0 = __floats2half2_rn(0.f, 0.f);
        __half2 accd = __floats2half2_rn(0.f, 0.f);
        float ar = 0.f;
        #pragma unroll
        for (int k = 0; k < 16; ++k) {
            unsigned xk = __shfl_sync(FULLMASK, xpack, k);
            __half2 hh = u2h2(xk);
            uint4 w = sPh[k * 32 + lane];
            acc0 = __hfma2(hh, u2h2(w.x), acc0);
            accd = __hfma2(hh, u2h2(w.y), accd);
            float2 hx = u2f2(xk);
            float2 wr = u2f2(w.z);
            ar = fmaf(hx.y, wr.y, fmaf(hx.x, wr.x, ar));
        }
        float a0 = __low2float(acc0) + __high2float(acc0);
        float ad = __low2float(accd) + __high2float(accd);
        // pair across adjacent lanes -> planar-pair store (even lanes write)
        float a0o = __shfl_xor_sync(FULLMASK, a0, 1);
        float ado = __shfl_xor_sync(FULLMASK, ad, 1);
        if (!(lane & 1))
            g_p1[node * 16 + (lane >> 1)] = make_uint2(h2u(a0, a0o), h2u(ad, ado));
        g_r1[node * 32 + lane] = ar + b1[lane];
    } else {
        int e = (blockIdx.x - PB) * blockDim.x + threadIdx.x;
        if (e >= E) return;
        int src, dst;
        if (g_is64) {
            const long long* p = (const long long*)ei;
            src = (int)p[e]; dst = (int)p[E + e];
        } else {
            const int* p = (const int*)ei;
            src = p[e]; dst = p[E + e];
        }
        g_esd[e] = (unsigned)src | ((unsigned)dst << 16);
        atomicAdd(&g_degi[dst], 1);
    }
}

// ---- layer-1 edge scatter: 16-lane sub-warp, lane owns feature PAIR ----
#define EPW1 4
__global__ void k_edge1(const float* __restrict__ ea, int E) {
    int tid = blockIdx.x * blockDim.x + threadIdx.x;
    int sw = tid >> 4;
    int sl = tid & 15;
    int e0 = sw * EPW1;
    if (e0 >= E) return;
    unsigned sd[EPW1];
    __half2  u2[EPW1];
    #pragma unroll
    for (int i = 0; i < EPW1; ++i) {
        int e = e0 + i;
        if (e < E) { sd[i] = g_esd[e]; u2[i] = __float2half2_rn(__ldg(&ea[e])); }
        else       { sd[i] = (unsigned)NMAX | ((unsigned)NMAX << 16);
                     u2[i] = __floats2half2_rn(0.f, 0.f); }
    }
    uint2 v[EPW1];
    #pragma unroll
    for (int i = 0; i < EPW1; ++i)
        v[i] = g_p1[(sd[i] & 0xFFFFu) * 16 + sl];
    #pragma unroll
    for (int i = 0; i < EPW1; ++i) {
        __half2 m = __hfma2(u2[i], u2h2(v[i].y), u2h2(v[i].x));
        atomicAdd(((__half2*)g_agg1) + (sd[i] >> 16) * 16 + sl, m);
    }
}

// ---- combine1 + fused layer-2 node precompute. Warp per node, split-k. ----
__global__ void k_gcomb1(const float* __restrict__ W2,     // (2,32,10)
                         const float* __restrict__ root2,  // (32,10)
                         const float* __restrict__ b2,
                         int n) {
    __shared__ uint4 sP2h[256];   // [k*16+j] {W0 pair, dW pair, root pair} fp16
    __shared__ float sB2[16];
    int tid = threadIdx.x;
    for (int i = tid; i < 256; i += blockDim.x) {
        int k = i >> 4, j = i & 15;
        float w0a = 0.f, w0b = 0.f, wda = 0.f, wdb = 0.f, ra = 0.f, rb = 0.f;
        if (j < 10) {
            w0a = W2[(2 * k) * 10 + j];       w0b = W2[(2 * k + 1) * 10 + j];
            wda = W2[320 + (2 * k) * 10 + j] - w0a;
            wdb = W2[320 + (2 * k + 1) * 10 + j] - w0b;
            ra  = root2[(2 * k) * 10 + j];    rb  = root2[(2 * k + 1) * 10 + j];
        }
        sP2h[i] = make_uint4(h2u(w0a, w0b), h2u(wda, wdb), h2u(ra, rb), 0u);
    }
    if (tid < 16) sB2[tid] = (tid < 10) ? ((const float*)b2)[tid] : 0.f;
    __syncthreads();
    int lane = tid & 31;
    int d = blockIdx.x * (blockDim.x >> 5) + (tid >> 5);
    if (d >= n) return;
    float inv = 1.0f / fmaxf((float)g_degi[d], 1.0f);
    float agg = __half2float(g_agg1[d * 32 + lane]);
    float h = fmaxf(agg * inv + g_r1[d * 32 + lane], 0.0f);
    // pack h pairs for half2 shuffle-GEMM (lanes 0-15 hold valid pairs)
    int jp = lane & 15;
    unsigned hpack = h2u(__shfl_sync(FULLMASK, h, 2 * jp),
                         __shfl_sync(FULLMASK, h, 2 * jp + 1));
    int j2 = lane & 15;
    int kbase = (lane >> 4) << 3;       // 0 for lanes 0-15, 8 for lanes 16-31
    __half2 acc0 = __floats2half2_rn(0.f, 0.f);
    __half2 accd = __floats2half2_rn(0.f, 0.f);
    float ar = 0.f;
    #pragma unroll
    for (int kk = 0; kk < 8; ++kk) {
        int k = kbase + kk;
        unsigned hk = __shfl_sync(FULLMASK, hpack, k);   // source lanes 0-15 only
        __half2 hh = u2h2(hk);
        uint4 w = sP2h[k * 16 + j2];
        acc0 = __hfma2(hh, u2h2(w.x), acc0);
        accd = __hfma2(hh, u2h2(w.y), accd);
        float2 hx = u2f2(hk);
        float2 wr = u2f2(w.z);
        ar = fmaf(hx.y, wr.y, fmaf(hx.x, wr.x, ar));
    }
    float a0 = __low2float(acc0) + __high2float(acc0);
    float ad = __low2float(accd) + __high2float(accd);
    a0 += __shfl_xor_sync(FULLMASK, a0, 16);
    ad += __shfl_xor_sync(FULLMASK, ad, 16);
    ar += __shfl_xor_sync(FULLMASK, ar, 16);
    // pair across adjacent lanes for planar-pair store
    float a0o = __shfl_xor_sync(FULLMASK, a0, 1);
    float ado = __shfl_xor_sync(FULLMASK, ad, 1);
    if (lane < 16) {
        if (!(lane & 1))
            g_p2[d * 8 + (lane >> 1)] = make_uint2(h2u(a0, a0o), h2u(ad, ado));
        g_r2[d * 16 + lane] = ar + sB2[lane];
    }
}

// ---- layer-2 edge scatter: 8-lane group, lane owns feature PAIR ----
#define EPW2 4
__global__ void k_edge2(const float* __restrict__ ea, int E) {
    int tid = blockIdx.x * blockDim.x + threadIdx.x;
    int grp = tid >> 3;
    int sl = tid & 7;
    int e0 = grp * EPW2;
    if (e0 >= E) return;
    unsigned sd[EPW2];
    __half2  u2[EPW2];
    #pragma unroll
    for (int i = 0; i < EPW2; ++i) {
        int e = e0 + i;
        if (e < E) { sd[i] = g_esd[e]; u2[i] = __float2half2_rn(__ldg(&ea[e])); }
        else       { sd[i] = (unsigned)NMAX | ((unsigned)NMAX << 16);
                     u2[i] = __floats2half2_rn(0.f, 0.f); }
    }
    uint2 v[EPW2];
    #pragma unroll
    for (int i = 0; i < EPW2; ++i)
        v[i] = g_p2[(sd[i] & 0xFFFFu) * 8 + sl];
    #pragma unroll
    for (int i = 0; i < EPW2; ++i) {
        if (sl < 5) {   // features 0..9 only (10..15 are zero columns)
            __half2 m = __hfma2(u2[i], u2h2(v[i].y), u2h2(v[i].x));
            atomicAdd(((__half2*)g_agg2) + (sd[i] >> 16) * 8 + sl, m);
        }
    }
}

// ---- combine2 + log_softmax. 16-lane group per node, half-warp masks. ----
__global__ void k_comb2(float* __restrict__ out, int n) {
    int tid = blockIdx.x * blockDim.x + threadIdx.x;
    int lane = threadIdx.x & 31;
    int half = lane >> 4;
    int sl = lane & 15;
    unsigned mask = half ? 0xFFFF0000u : 0x0000FFFFu;
    int d = tid >> 4;
    bool valid = (d < n);
    float inv = valid ? (1.0f / fmaxf((float)g_degi[d], 1.0f)) : 1.0f;
    float agg = valid ? __half2float(g_agg2[d * 16 + sl]) : 0.f;
    float z = valid ? (agg * inv + g_r2[d * 16 + sl]) : 0.f;
    float zm = (sl < 10) ? z : -1e30f;
    float m = zm;
    #pragma unroll
    for (int o = 8; o >= 1; o >>= 1) m = fmaxf(m, __shfl_xor_sync(mask, m, o));
    float ex = (sl < 10) ? __expf(z - m) : 0.f;
    float s = ex;
    #pragma unroll
    for (int o = 8; o >= 1; o >>= 1) s += __shfl_xor_sync(mask, s, o);
    float l = m + logf(s);
    if (valid && sl < 10) out[d * 10 + sl] = z - l;
}

extern "C" void kernel_launch(void* const* d_in, const int* in_sizes, int n_in,
                              void* d_out, int out_size) {
    const float* x     = (const float*)d_in[0];
    const void*  ei    = d_in[1];
    const float* ea    = (const float*)d_in[2];
    const float* W1    = (const float*)d_in[3];
    const float* root1 = (const float*)d_in[4];
    const float* b1    = (const float*)d_in[5];
    const float* W2    = (const float*)d_in[6];
    const float* root2 = (const float*)d_in[7];
    const float* b2    = (const float*)d_in[8];
    float* out = (float*)d_out;

    int N = in_sizes[0] / 32;
    int E = in_sizes[2];

    {
        int zthreads = (N + 1) * 4;                       // agg1 float4 elems dominate
        k_init<<<(zthreads + 255) / 256, 256>>>(ei, N);
    }
    int PB = (N + 7) / 8;
    int DB = (E + 255) / 256;
    k_fused1<<<PB + DB, 256>>>(x, W1, root1, b1, ei, N, E, PB);
    {
        long long th = ((long long)(E + EPW1 - 1) / EPW1) * 16;
        k_edge1<<<(int)((th + 255) / 256), 256>>>(ea, E);
    }
    k_gcomb1<<<(N + 7) / 8, 256>>>(W2, root2, b2, N);
    {
        long long th = ((long long)(E + EPW2 - 1) / EPW2) * 8;
        k_edge2<<<(int)((th + 255) / 256), 256>>>(ea, E);
    }
    {
        long long th = (long long)N * 16;
        k_comb2<<<(int)((th + 255) / 256), 256>>>(out, N);
    }
}

// round 15
// speedup vs baseline: 1.8909x; 1.0182x over previous
#include <cuda_runtime.h>
#include <cuda_fp16.h>

// splineGCN: 2-layer SplineConv (K=2), N=50000, E=1.6M, 32 -> 32 -> 10, log_softmax.
// Atomic-RED skeleton; HFMA2 fp16-pair GEMMs with fp32 root path fed by fp32
// smem (no per-iter converts); planar-pair p1/p2/r1 tables; fp16x2 RED.

#define NMAX 50000
#define EMAX 1600000
#define FULLMASK 0xffffffffu

// ---- scratch (dummy node/agg row at index NMAX) ----
__device__ uint2    g_p1  [(NMAX + 1) * 16];   // {h0pair, hdpair} per (node, feat-pair)
__device__ unsigned g_r1p [NMAX * 16];         // (x@root1+b1) fp16 pairs
__device__ __half   g_agg1[(NMAX + 1) * 32];   // fp16 accumulators (RED.F16x2)
__device__ uint2    g_p2  [(NMAX + 1) * 8];    // {g0pair, gdpair} (cols 10..15 zero)
__device__ float    g_r2  [NMAX * 16];         // fp32 (feeds outputs directly)
__device__ __half   g_agg2[(NMAX + 1) * 16];
__device__ int      g_degi[NMAX];
__device__ unsigned g_esd [EMAX];              // src | dst<<16
__device__ int      g_is64;

static __device__ __forceinline__ unsigned h2u(float a, float b) {
    __half2 h = __floats2half2_rn(a, b);
    return *reinterpret_cast<unsigned*>(&h);
}
static __device__ __forceinline__ float2 u2f2(unsigned v) {
    __half2 h = *reinterpret_cast<__half2*>(&v);
    return __half22float2(h);
}
static __device__ __forceinline__ __half2 u2h2(unsigned v) {
    return *reinterpret_cast<__half2*>(&v);
}

// ---- init: vectorized zeroing + dtype detect + dummy rows ----
__global__ void k_init(const void* __restrict__ ei, int n) {
    int i = blockIdx.x * blockDim.x + threadIdx.x;
    float4 z = make_float4(0.f, 0.f, 0.f, 0.f);
    if (i < (n + 1) * 4) ((float4*)g_agg1)[i] = z;          // 32 halfs = 4 float4 / node
    if (i < (n + 1) * 2) ((float4*)g_agg2)[i] = z;          // 16 halfs = 2 float4 / node
    if (i < (n + 3) / 4) ((int4*)g_degi)[i] = make_int4(0, 0, 0, 0);
    if (i < 16) g_p1[NMAX * 16 + i] = make_uint2(0u, 0u);
    if (i < 8)  g_p2[NMAX * 8 + i]  = make_uint2(0u, 0u);
    if (i == 0) {
        const int* p = (const int*)ei;
        int ok64 = 1;
        #pragma unroll
        for (int k = 0; k < 32; ++k)
            if (p[2 * k + 1] != 0) ok64 = 0;
        g_is64 = ok64;
    }
}

// ---- fused: prep1 (blocks < PB) + decode/degree (blocks >= PB) ----
__global__ void k_fused1(const float* __restrict__ x,
                         const float* __restrict__ W1,     // (2,32,32)
                         const float* __restrict__ root1,  // (32,32)
                         const float* __restrict__ b1,
                         const void* __restrict__ ei,
                         int n, int E, int PB) {
    if (blockIdx.x < PB) {
        __shared__ uint2  sW[512];   // [k*32+j] {W0 pair, dW pair} fp16
        __shared__ float2 sR[512];   // [k*32+j] root pair fp32
        for (int i = threadIdx.x; i < 512; i += blockDim.x) {
            int k = i >> 5, j = i & 31;
            float w0a = W1[(2 * k) * 32 + j],     w0b = W1[(2 * k + 1) * 32 + j];
            float w1a = W1[1024 + (2 * k) * 32 + j], w1b = W1[1024 + (2 * k + 1) * 32 + j];
            sW[i] = make_uint2(h2u(w0a, w0b), h2u(w1a - w0a, w1b - w0b));
            sR[i] = make_float2(root1[(2 * k) * 32 + j], root1[(2 * k + 1) * 32 + j]);
        }
        __syncthreads();
        int lane = threadIdx.x & 31;
        int node = blockIdx.x * (blockDim.x >> 5) + (threadIdx.x >> 5);
        if (node >= n) return;
        unsigned xpack;
        {
            int j = lane & 15;
            float2 xp = ((const float2*)(x + node * 32))[j];
            xpack = h2u(xp.x, xp.y);
        }
        __half2 acc0 = __floats2half2_rn(0.f, 0.f);
        __half2 accd = __floats2half2_rn(0.f, 0.f);
        float ar = 0.f;
        #pragma unroll
        for (int k = 0; k < 16; ++k) {
            unsigned xk = __shfl_sync(FULLMASK, xpack, k);
            __half2 hh = u2h2(xk);
            uint2  w = sW[k * 32 + lane];
            float2 r = sR[k * 32 + lane];
            acc0 = __hfma2(hh, u2h2(w.x), acc0);
            accd = __hfma2(hh, u2h2(w.y), accd);
            float2 hx = u2f2(xk);
            ar = fmaf(hx.y, r.y, fmaf(hx.x, r.x, ar));
        }
        float a0 = __low2float(acc0) + __high2float(acc0);
        float ad = __low2float(accd) + __high2float(accd);
        ar += b1[lane];
        float a0o = __shfl_xor_sync(FULLMASK, a0, 1);
        float ado = __shfl_xor_sync(FULLMASK, ad, 1);
        float aro = __shfl_xor_sync(FULLMASK, ar, 1);
        if (!(lane & 1)) {
            int o = node * 16 + (lane >> 1);
            g_p1[o]  = make_uint2(h2u(a0, a0o), h2u(ad, ado));
            g_r1p[o] = h2u(ar, aro);
        }
    } else {
        int e = (blockIdx.x - PB) * blockDim.x + threadIdx.x;
        if (e >= E) return;
        int src, dst;
        if (g_is64) {
            const long long* p = (const long long*)ei;
            src = (int)p[e]; dst = (int)p[E + e];
        } else {
            const int* p = (const int*)ei;
            src = p[e]; dst = p[E + e];
        }
        g_esd[e] = (unsigned)src | ((unsigned)dst << 16);
        atomicAdd(&g_degi[dst], 1);
    }
}

// ---- layer-1 edge scatter: 16-lane sub-warp, lane owns feature PAIR ----
#define EPW1 6
__global__ void k_edge1(const float* __restrict__ ea, int E) {
    int tid = blockIdx.x * blockDim.x + threadIdx.x;
    int sw = tid >> 4;
    int sl = tid & 15;
    int e0 = sw * EPW1;
    if (e0 >= E) return;
    unsigned sd[EPW1];
    __half2  u2[EPW1];
    #pragma unroll
    for (int i = 0; i < EPW1; ++i) {
        int e = e0 + i;
        if (e < E) { sd[i] = g_esd[e]; u2[i] = __float2half2_rn(__ldg(&ea[e])); }
        else       { sd[i] = (unsigned)NMAX | ((unsigned)NMAX << 16);
                     u2[i] = __floats2half2_rn(0.f, 0.f); }
    }
    uint2 v[EPW1];
    #pragma unroll
    for (int i = 0; i < EPW1; ++i)
        v[i] = g_p1[(sd[i] & 0xFFFFu) * 16 + sl];
    #pragma unroll
    for (int i = 0; i < EPW1; ++i) {
        __half2 m = __hfma2(u2[i], u2h2(v[i].y), u2h2(v[i].x));
        atomicAdd(((__half2*)g_agg1) + (sd[i] >> 16) * 16 + sl, m);
    }
}

// ---- combine1 + fused layer-2 node precompute. Warp per node, split-k. ----
// h formed directly as fp16 pairs from planar agg/r1 (one HFMA2 + HMAX2).
__global__ void k_gcomb1(const float* __restrict__ W2,     // (2,32,10)
                         const float* __restrict__ root2,  // (32,10)
                         const float* __restrict__ b2,
                         int n) {
    __shared__ uint2  sW2[256];   // [k*16+j] {W0 pair, dW pair} fp16
    __shared__ float2 sR2[256];   // [k*16+j] root pair fp32
    __shared__ float  sB2[16];
    int tid = threadIdx.x;
    for (int i = tid; i < 256; i += blockDim.x) {
        int k = i >> 4, j = i & 15;
        float w0a = 0.f, w0b = 0.f, wda = 0.f, wdb = 0.f, ra = 0.f, rb = 0.f;
        if (j < 10) {
            w0a = W2[(2 * k) * 10 + j];       w0b = W2[(2 * k + 1) * 10 + j];
            wda = W2[320 + (2 * k) * 10 + j] - w0a;
            wdb = W2[320 + (2 * k + 1) * 10 + j] - w0b;
            ra  = root2[(2 * k) * 10 + j];    rb  = root2[(2 * k + 1) * 10 + j];
        }
        sW2[i] = make_uint2(h2u(w0a, w0b), h2u(wda, wdb));
        sR2[i] = make_float2(ra, rb);
    }
    if (tid < 16) sB2[tid] = (tid < 10) ? ((const float*)b2)[tid] : 0.f;
    __syncthreads();
    int lane = tid & 31;
    int d = blockIdx.x * (blockDim.x >> 5) + (tid >> 5);
    if (d >= n) return;
    float inv = 1.0f / fmaxf((float)g_degi[d], 1.0f);
    __half2 inv2 = __float2half2_rn(inv);
    int jp = lane & 15;
    __half2 aggp = ((const __half2*)g_agg1)[d * 16 + jp];
    __half2 r1p  = u2h2(g_r1p[d * 16 + jp]);
    __half2 zero2 = __floats2half2_rn(0.f, 0.f);
    __half2 hp = __hmax2(__hfma2(aggp, inv2, r1p), zero2);
    unsigned hpack = *reinterpret_cast<unsigned*>(&hp);
    int j2 = lane & 15;
    int kbase = (lane >> 4) << 3;       // 0 for lanes 0-15, 8 for lanes 16-31
    __half2 acc0 = zero2;
    __half2 accd = zero2;
    float ar = 0.f;
    #pragma unroll
    for (int kk = 0; kk < 8; ++kk) {
        int k = kbase + kk;
        unsigned hk = __shfl_sync(FULLMASK, hpack, k);   // source lanes 0-15 only
        __half2 hh = u2h2(hk);
        uint2  w = sW2[k * 16 + j2];
        float2 r = sR2[k * 16 + j2];
        acc0 = __hfma2(hh, u2h2(w.x), acc0);
        accd = __hfma2(hh, u2h2(w.y), accd);
        float2 hx = u2f2(hk);
        ar = fmaf(hx.y, r.y, fmaf(hx.x, r.x, ar));
    }
    float a0 = __low2float(acc0) + __high2float(acc0);
    float ad = __low2float(accd) + __high2float(accd);
    a0 += __shfl_xor_sync(FULLMASK, a0, 16);
    ad += __shfl_xor_sync(FULLMASK, ad, 16);
    ar += __shfl_xor_sync(FULLMASK, ar, 16);
    float a0o = __shfl_xor_sync(FULLMASK, a0, 1);
    float ado = __shfl_xor_sync(FULLMASK, ad, 1);
    if (lane < 16) {
        if (!(lane & 1))
            g_p2[d * 8 + (lane >> 1)] = make_uint2(h2u(a0, a0o), h2u(ad, ado));
        g_r2[d * 16 + lane] = ar + sB2[lane];
    }
}

// ---- layer-2 edge scatter: 8-lane group, lane owns feature PAIR ----
#define EPW2 6
__global__ void k_edge2(const float* __restrict__ ea, int E) {
    int tid = blockIdx.x * blockDim.x + threadIdx.x;
    int grp = tid >> 3;
    int sl = tid & 7;
    int e0 = grp * EPW2;
    if (e0 >= E) return;
    unsigned sd[EPW2];
    __half2  u2[EPW2];
    #pragma unroll
    for (int i = 0; i < EPW2; ++i) {
        int e = e0 + i;
        if (e < E) { sd[i] = g_esd[e]; u2[i] = __float2half2_rn(__ldg(&ea[e])); }
        else       { sd[i] = (unsigned)NMAX | ((unsigned)NMAX << 16);
                     u2[i] = __floats2half2_rn(0.f, 0.f); }
    }
    uint2 v[EPW2];
    #pragma unroll
    for (int i = 0; i < EPW2; ++i)
        v[i] = g_p2[(sd[i] & 0xFFFFu) * 8 + sl];
    #pragma unroll
    for (int i = 0; i < EPW2; ++i) {
        if (sl < 5) {   // features 0..9 only (10..15 are zero columns)
            __half2 m = __hfma2(u2[i], u2h2(v[i].y), u2h2(v[i].x));
            atomicAdd(((__half2*)g_agg2) + (sd[i] >> 16) * 8 + sl, m);
        }
    }
}

// ---- combine2 + log_softmax. 16-lane group per node, half-warp masks. ----
__global__ void k_comb2(float* __restrict__ out, int n) {
    int tid = blockIdx.x * blockDim.x + threadIdx.x;
    int lane = threadIdx.x & 31;
    int half = lane >> 4;
    int sl = lane & 15;
    unsigned mask = half ? 0xFFFF0000u : 0x0000FFFFu;
    int d = tid >> 4;
    bool valid = (d < n);
    float inv = valid ? (1.0f / fmaxf((float)g_degi[d], 1.0f)) : 1.0f;
    float agg = valid ? __half2float(g_agg2[d * 16 + sl]) : 0.f;
    float z = valid ? (agg * inv + g_r2[d * 16 + sl]) : 0.f;
    float zm = (sl < 10) ? z : -1e30f;
    float m = zm;
    #pragma unroll
    for (int o = 8; o >= 1; o >>= 1) m = fmaxf(m, __shfl_xor_sync(mask, m, o));
    float ex = (sl < 10) ? __expf(z - m) : 0.f;
    float s = ex;
    #pragma unroll
    for (int o = 8; o >= 1; o >>= 1) s += __shfl_xor_sync(mask, s, o);
    float l = m + logf(s);
    if (valid && sl < 10) out[d * 10 + sl] = z - l;
}

extern "C" void kernel_launch(void* const* d_in, const int* in_sizes, int n_in,
                              void* d_out, int out_size) {
    const float* x     = (const float*)d_in[0];
    const void*  ei    = d_in[1];
    const float* ea    = (const float*)d_in[2];
    const float* W1    = (const float*)d_in[3];
    const float* root1 = (const float*)d_in[4];
    const float* b1    = (const float*)d_in[5];
    const float* W2    = (const float*)d_in[6];
    const float* root2 = (const float*)d_in[7];
    const float* b2    = (const float*)d_in[8];
    float* out = (float*)d_out;

    int N = in_sizes[0] / 32;
    int E = in_sizes[2];

    {
        int zthreads = (N + 1) * 4;                       // agg1 float4 elems dominate
        k_init<<<(zthreads + 255) / 256, 256>>>(ei, N);
    }
    int PB = (N + 7) / 8;
    int DB = (E + 255) / 256;
    k_fused1<<<PB + DB, 256>>>(x, W1, root1, b1, ei, N, E, PB);
    {
        long long th = ((long long)(E + EPW1 - 1) / EPW1) * 16;
        k_edge1<<<(int)((th + 255) / 256), 256>>>(ea, E);
    }
    k_gcomb1<<<(N + 7) / 8, 256>>>(W2, root2, b2, N);
    {
        long long th = ((long long)(E + EPW2 - 1) / EPW2) * 8;
        k_edge2<<<(int)((th + 255) / 256), 256>>>(ea, E);
    }
    {
        long long th = (long long)N * 16;
        k_comb2<<<(int)((th + 255) / 256), 256>>>(out, N);
    }
}

// round 16
// speedup vs baseline: 1.9094x; 1.0098x over previous
#include <cuda_runtime.h>
#include <cuda_fp16.h>

// splineGCN: 2-layer SplineConv (K=2), N=50000, E=1.6M, 32 -> 32 -> 10, log_softmax.
// Atomic-RED skeleton; PURE fp16 HFMA2 GEMM loops (w0/dw/root in one uint4);
// planar-pair p1/p2/r1 tables; fp16x2 RED aggregation; agg zeroing folded
// into fused1 as a third block range.

#define NMAX 50000
#define EMAX 1600000
#define FULLMASK 0xffffffffu

// ---- scratch (dummy node/agg row at index NMAX) ----
__device__ uint2    g_p1  [(NMAX + 1) * 16];   // {h0pair, hdpair} per (node, feat-pair)
__device__ unsigned g_r1p [NMAX * 16];         // (x@root1+b1) fp16 pairs
__device__ __half   g_agg1[(NMAX + 1) * 32];   // fp16 accumulators (RED.F16x2)
__device__ uint2    g_p2  [(NMAX + 1) * 8];    // {g0pair, gdpair} (cols 10..15 zero)
__device__ float    g_r2  [NMAX * 16];         // fp32 (feeds outputs directly)
__device__ __half   g_agg2[(NMAX + 1) * 16];
__device__ int      g_degi[NMAX];
__device__ unsigned g_esd [EMAX];              // src | dst<<16
__device__ int      g_is64;

static __device__ __forceinline__ unsigned h2u(float a, float b) {
    __half2 h = __floats2half2_rn(a, b);
    return *reinterpret_cast<unsigned*>(&h);
}
static __device__ __forceinline__ __half2 u2h2(unsigned v) {
    return *reinterpret_cast<__half2*>(&v);
}

// ---- init: degi zero + dtype detect + dummy rows (agg zeroing is in fused1) ----
__global__ void k_init(const void* __restrict__ ei, int n) {
    int i = blockIdx.x * blockDim.x + threadIdx.x;
    if (i < (n + 3) / 4) ((int4*)g_degi)[i] = make_int4(0, 0, 0, 0);
    if (i < 16) g_p1[NMAX * 16 + i] = make_uint2(0u, 0u);
    if (i < 8)  g_p2[NMAX * 8 + i]  = make_uint2(0u, 0u);
    if (i == 0) {
        const int* p = (const int*)ei;
        int ok64 = 1;
        #pragma unroll
        for (int k = 0; k < 32; ++k)
            if (p[2 * k + 1] != 0) ok64 = 0;
        g_is64 = ok64;
    }
}

// ---- fused: prep1 | decode/degree | agg zeroing (three block ranges) ----
__global__ void k_fused1(const float* __restrict__ x,
                         const float* __restrict__ W1,     // (2,32,32)
                         const float* __restrict__ root1,  // (32,32)
                         const float* __restrict__ b1,
                         const void* __restrict__ ei,
                         int n, int E, int PB, int DB) {
    if (blockIdx.x < (unsigned)PB) {
        // sPh[k*32+j] = {W0 pair, dW pair, root pair, 0} fp16
        __shared__ uint4 sPh[512];
        for (int i = threadIdx.x; i < 512; i += blockDim.x) {
            int k = i >> 5, j = i & 31;
            float w0a = W1[(2 * k) * 32 + j],     w0b = W1[(2 * k + 1) * 32 + j];
            float w1a = W1[1024 + (2 * k) * 32 + j], w1b = W1[1024 + (2 * k + 1) * 32 + j];
            float ra  = root1[(2 * k) * 32 + j],  rb  = root1[(2 * k + 1) * 32 + j];
            sPh[i] = make_uint4(h2u(w0a, w0b), h2u(w1a - w0a, w1b - w0b), h2u(ra, rb), 0u);
        }
        __syncthreads();
        int lane = threadIdx.x & 31;
        int node = blockIdx.x * (blockDim.x >> 5) + (threadIdx.x >> 5);
        if (node >= n) return;
        unsigned xpack;
        {
            int j = lane & 15;
            float2 xp = ((const float2*)(x + node * 32))[j];
            xpack = h2u(xp.x, xp.y);
        }
        __half2 zero2 = __floats2half2_rn(0.f, 0.f);
        __half2 acc0 = zero2, accd = zero2, accr = zero2;
        #pragma unroll
        for (int k = 0; k < 16; ++k) {
            unsigned xk = __shfl_sync(FULLMASK, xpack, k);
            __half2 hh = u2h2(xk);
            uint4 w = sPh[k * 32 + lane];
            acc0 = __hfma2(hh, u2h2(w.x), acc0);
            accd = __hfma2(hh, u2h2(w.y), accd);
            accr = __hfma2(hh, u2h2(w.z), accr);
        }
        float a0 = __low2float(acc0) + __high2float(acc0);
        float ad = __low2float(accd) + __high2float(accd);
        float ar = __low2float(accr) + __high2float(accr) + b1[lane];
        float a0o = __shfl_xor_sync(FULLMASK, a0, 1);
        float ado = __shfl_xor_sync(FULLMASK, ad, 1);
        float aro = __shfl_xor_sync(FULLMASK, ar, 1);
        if (!(lane & 1)) {
            int o = node * 16 + (lane >> 1);
            g_p1[o]  = make_uint2(h2u(a0, a0o), h2u(ad, ado));
            g_r1p[o] = h2u(ar, aro);
        }
    } else if (blockIdx.x < (unsigned)(PB + DB)) {
        int e = (blockIdx.x - PB) * blockDim.x + threadIdx.x;
        if (e >= E) return;
        int src, dst;
        if (g_is64) {
            const long long* p = (const long long*)ei;
            src = (int)p[e]; dst = (int)p[E + e];
        } else {
            const int* p = (const int*)ei;
            src = p[e]; dst = p[E + e];
        }
        g_esd[e] = (unsigned)src | ((unsigned)dst << 16);
        atomicAdd(&g_degi[dst], 1);
    } else {
        // agg zeroing: agg1 has (n+1)*4 float4s, agg2 has (n+1)*2 float4s
        int i = (blockIdx.x - PB - DB) * blockDim.x + threadIdx.x;
        float4 z = make_float4(0.f, 0.f, 0.f, 0.f);
        int n1 = (n + 1) * 4;
        if (i < n1) ((float4*)g_agg1)[i] = z;
        else {
            int i2 = i - n1;
            if (i2 < (n + 1) * 2) ((float4*)g_agg2)[i2] = z;
        }
    }
}

// ---- layer-1 edge scatter: 16-lane sub-warp, lane owns feature PAIR ----
#define EPW1 6
__global__ void k_edge1(const float* __restrict__ ea, int E) {
    int tid = blockIdx.x * blockDim.x + threadIdx.x;
    int sw = tid >> 4;
    int sl = tid & 15;
    int e0 = sw * EPW1;
    if (e0 >= E) return;
    unsigned sd[EPW1];
    __half2  u2[EPW1];
    #pragma unroll
    for (int i = 0; i < EPW1; ++i) {
        int e = e0 + i;
        if (e < E) { sd[i] = g_esd[e]; u2[i] = __float2half2_rn(__ldg(&ea[e])); }
        else       { sd[i] = (unsigned)NMAX | ((unsigned)NMAX << 16);
                     u2[i] = __floats2half2_rn(0.f, 0.f); }
    }
    uint2 v[EPW1];
    #pragma unroll
    for (int i = 0; i < EPW1; ++i)
        v[i] = g_p1[(sd[i] & 0xFFFFu) * 16 + sl];
    #pragma unroll
    for (int i = 0; i < EPW1; ++i) {
        __half2 m = __hfma2(u2[i], u2h2(v[i].y), u2h2(v[i].x));
        atomicAdd(((__half2*)g_agg1) + (sd[i] >> 16) * 16 + sl, m);
    }
}

// ---- combine1 + fused layer-2 node precompute. Warp per node, split-k. ----
// Pure fp16 loop: one LDS.128 + SHFL + 3 HFMA2 per k-pair.
__global__ void k_gcomb1(const float* __restrict__ W2,     // (2,32,10)
                         const float* __restrict__ root2,  // (32,10)
                         const float* __restrict__ b2,
                         int n) {
    __shared__ uint4 sP2h[256];   // [k*16+j] {W0 pair, dW pair, root pair, 0} fp16
    __shared__ float sB2[16];
    int tid = threadIdx.x;
    for (int i = tid; i < 256; i += blockDim.x) {
        int k = i >> 4, j = i & 15;
        float w0a = 0.f, w0b = 0.f, wda = 0.f, wdb = 0.f, ra = 0.f, rb = 0.f;
        if (j < 10) {
            w0a = W2[(2 * k) * 10 + j];       w0b = W2[(2 * k + 1) * 10 + j];
            wda = W2[320 + (2 * k) * 10 + j] - w0a;
            wdb = W2[320 + (2 * k + 1) * 10 + j] - w0b;
            ra  = root2[(2 * k) * 10 + j];    rb  = root2[(2 * k + 1) * 10 + j];
        }
        sP2h[i] = make_uint4(h2u(w0a, w0b), h2u(wda, wdb), h2u(ra, rb), 0u);
    }
    if (tid < 16) sB2[tid] = (tid < 10) ? ((const float*)b2)[tid] : 0.f;
    __syncthreads();
    int lane = tid & 31;
    int d = blockIdx.x * (blockDim.x >> 5) + (tid >> 5);
    if (d >= n) return;
    float inv = 1.0f / fmaxf((float)g_degi[d], 1.0f);
    __half2 inv2 = __float2half2_rn(inv);
    int jp = lane & 15;
    __half2 aggp = ((const __half2*)g_agg1)[d * 16 + jp];
    __half2 r1p  = u2h2(g_r1p[d * 16 + jp]);
    __half2 zero2 = __floats2half2_rn(0.f, 0.f);
    __half2 hp = __hmax2(__hfma2(aggp, inv2, r1p), zero2);
    unsigned hpack = *reinterpret_cast<unsigned*>(&hp);
    int j2 = lane & 15;
    int kbase = (lane >> 4) << 3;       // 0 for lanes 0-15, 8 for lanes 16-31
    __half2 acc0 = zero2, accd = zero2, accr = zero2;
    #pragma unroll
    for (int kk = 0; kk < 8; ++kk) {
        int k = kbase + kk;
        unsigned hk = __shfl_sync(FULLMASK, hpack, k);   // source lanes 0-15 only
        __half2 hh = u2h2(hk);
        uint4 w = sP2h[k * 16 + j2];
        acc0 = __hfma2(hh, u2h2(w.x), acc0);
        accd = __hfma2(hh, u2h2(w.y), accd);
        accr = __hfma2(hh, u2h2(w.z), accr);
    }
    float a0 = __low2float(acc0) + __high2float(acc0);
    float ad = __low2float(accd) + __high2float(accd);
    float ar = __low2float(accr) + __high2float(accr);
    a0 += __shfl_xor_sync(FULLMASK, a0, 16);
    ad += __shfl_xor_sync(FULLMASK, ad, 16);
    ar += __shfl_xor_sync(FULLMASK, ar, 16);
    float a0o = __shfl_xor_sync(FULLMASK, a0, 1);
    float ado = __shfl_xor_sync(FULLMASK, ad, 1);
    if (lane < 16) {
        if (!(lane & 1))
            g_p2[d * 8 + (lane >> 1)] = make_uint2(h2u(a0, a0o), h2u(ad, ado));
        g_r2[d * 16 + lane] = ar + sB2[lane];
    }
}

// ---- layer-2 edge scatter: 8-lane group, lane owns feature PAIR ----
#define EPW2 6
__global__ void k_edge2(const float* __restrict__ ea, int E) {
    int tid = blockIdx.x * blockDim.x + threadIdx.x;
    int grp = tid >> 3;
    int sl = tid & 7;
    int e0 = grp * EPW2;
    if (e0 >= E) return;
    unsigned sd[EPW2];
    __half2  u2[EPW2];
    #pragma unroll
    for (int i = 0; i < EPW2; ++i) {
        int e = e0 + i;
        if (e < E) { sd[i] = g_esd[e]; u2[i] = __float2half2_rn(__ldg(&ea[e])); }
        else       { sd[i] = (unsigned)NMAX | ((unsigned)NMAX << 16);
                     u2[i] = __floats2half2_rn(0.f, 0.f); }
    }
    uint2 v[EPW2];
    #pragma unroll
    for (int i = 0; i < EPW2; ++i)
        v[i] = g_p2[(sd[i] & 0xFFFFu) * 8 + sl];
    #pragma unroll
    for (int i = 0; i < EPW2; ++i) {
        if (sl < 5) {   // features 0..9 only (10..15 are zero columns)
            __half2 m = __hfma2(u2[i], u2h2(v[i].y), u2h2(v[i].x));
            atomicAdd(((__half2*)g_agg2) + (sd[i] >> 16) * 8 + sl, m);
        }
    }
}

// ---- combine2 + log_softmax. 16-lane group per node, half-warp masks. ----
__global__ void k_comb2(float* __restrict__ out, int n) {
    int tid = blockIdx.x * blockDim.x + threadIdx.x;
    int lane = threadIdx.x & 31;
    int half = lane >> 4;
    int sl = lane & 15;
    unsigned mask = half ? 0xFFFF0000u : 0x0000FFFFu;
    int d = tid >> 4;
    bool valid = (d < n);
    float inv = valid ? (1.0f / fmaxf((float)g_degi[d], 1.0f)) : 1.0f;
    float agg = valid ? __half2float(g_agg2[d * 16 + sl]) : 0.f;
    float z = valid ? (agg * inv + g_r2[d * 16 + sl]) : 0.f;
    float zm = (sl < 10) ? z : -1e30f;
    float m = zm;
    #pragma unroll
    for (int o = 8; o >= 1; o >>= 1) m = fmaxf(m, __shfl_xor_sync(mask, m, o));
    float ex = (sl < 10) ? __expf(z - m) : 0.f;
    float s = ex;
    #pragma unroll
    for (int o = 8; o >= 1; o >>= 1) s += __shfl_xor_sync(mask, s, o);
    float l = m + logf(s);
    if (valid && sl < 10) out[d * 10 + sl] = z - l;
}

extern "C" void kernel_launch(void* const* d_in, const int* in_sizes, int n_in,
                              void* d_out, int out_size) {
    const float* x     = (const float*)d_in[0];
    const void*  ei    = d_in[1];
    const float* ea    = (const float*)d_in[2];
    const float* W1    = (const float*)d_in[3];
    const float* root1 = (const float*)d_in[4];
    const float* b1    = (const float*)d_in[5];
    const float* W2    = (const float*)d_in[6];
    const float* root2 = (const float*)d_in[7];
    const float* b2    = (const float*)d_in[8];
    float* out = (float*)d_out;

    int N = in_sizes[0] / 32;
    int E = in_sizes[2];

    k_init<<<(N / 4 + 256) / 256, 256>>>(ei, N);
    int PB = (N + 7) / 8;                              // prep1 blocks
    int DB = (E + 255) / 256;                          // decode blocks
    int ZB = ((N + 1) * 6 + 255) / 256;                // agg-zero blocks (float4s)
    k_fused1<<<PB + DB + ZB, 256>>>(x, W1, root1, b1, ei, N, E, PB, DB);
    {
        long long th = ((long long)(E + EPW1 - 1) / EPW1) * 16;
        k_edge1<<<(int)((th + 255) / 256), 256>>>(ea, E);
    }
    k_gcomb1<<<(N + 7) / 8, 256>>>(W2, root2, b2, N);
    {
        long long th = ((long long)(E + EPW2 - 1) / EPW2) * 8;
        k_edge2<<<(int)((th + 255) / 256), 256>>>(ea, E);
    }
    {
        long long th = (long long)N * 16;
        k_comb2<<<(int)((th + 255) / 256), 256>>>(out, N);
    }
}